// round 1
// baseline (speedup 1.0000x reference)
#include <cuda_runtime.h>
#include <cuda_bf16.h>
#include <math.h>

// Problem dims (fixed by reference)
#define BB 2
#define SS 2048
#define DD 192
#define HH 16
#define HD 128
#define NT (BB*SS)        // 4096 tokens
#define NF (HH*HD)        // 2048 features

// ---------------- scratch (device globals; no allocations allowed) ----------
__device__ float g_q[NT * NF];     // token-major [t][h*128+d]
__device__ float g_k[NT * NF];
__device__ float g_v[NT * NF];
__device__ float g_a[NT * NF];     // attention output, token-major
__device__ float g_cos[SS * 64];
__device__ float g_sin[SS * 64];

// ---------------- RoPE table (fp64-accurate) --------------------------------
__global__ void rope_table_kernel() {
    int i = blockIdx.x * blockDim.x + threadIdx.x;
    if (i >= SS * 64) return;
    int s = i >> 6, f = i & 63;
    // inv_freq = 1e6 ^ (-2f/128); ln(1e6) = 13.815510557964274
    double e = ((double)(2 * f) / 128.0) * 13.815510557964274;
    double invf = exp(-e);
    double ph = (double)s * invf;
    g_cos[i] = (float)cos(ph);
    g_sin[i] = (float)sin(ph);
}

// ---------------- Tiled SGEMM: C[M][N] = A[M][K] * W[N][K]^T ----------------
// BM=BN=64, BK=16, 256 threads, 4x4 microtile per thread.
#define BM 64
#define BN 64
#define BK 16

__global__ __launch_bounds__(256) void gemm_nt_kernel(
    const float* __restrict__ A,
    const float* __restrict__ W0, const float* __restrict__ W1, const float* __restrict__ W2,
    float* __restrict__ C0, float* __restrict__ C1, float* __restrict__ C2,
    int M, int N, int K)
{
    const float* __restrict__ W = (blockIdx.z == 0) ? W0 : (blockIdx.z == 1) ? W1 : W2;
    float* __restrict__ C = (blockIdx.z == 0) ? C0 : (blockIdx.z == 1) ? C1 : C2;

    __shared__ float As[BK][BM];
    __shared__ float Bs[BK][BN];

    int tid = threadIdx.x;
    int tx = tid & 15, ty = tid >> 4;
    int m0 = blockIdx.x * BM;
    int n0 = blockIdx.y * BN;

    int lr = tid >> 2;            // 0..63 row within tile
    int lc = (tid & 3) << 2;      // 0,4,8,12

    float acc[4][4] = {};

    for (int k0 = 0; k0 < K; k0 += BK) {
        float4 av = *(const float4*)(A + (size_t)(m0 + lr) * K + k0 + lc);
        As[lc + 0][lr] = av.x; As[lc + 1][lr] = av.y;
        As[lc + 2][lr] = av.z; As[lc + 3][lr] = av.w;
        float4 bv = *(const float4*)(W + (size_t)(n0 + lr) * K + k0 + lc);
        Bs[lc + 0][lr] = bv.x; Bs[lc + 1][lr] = bv.y;
        Bs[lc + 2][lr] = bv.z; Bs[lc + 3][lr] = bv.w;
        __syncthreads();

        #pragma unroll
        for (int kk = 0; kk < BK; kk++) {
            float4 a = *(const float4*)(&As[kk][ty * 4]);
            float4 b = *(const float4*)(&Bs[kk][tx * 4]);
            acc[0][0] += a.x * b.x; acc[0][1] += a.x * b.y; acc[0][2] += a.x * b.z; acc[0][3] += a.x * b.w;
            acc[1][0] += a.y * b.x; acc[1][1] += a.y * b.y; acc[1][2] += a.y * b.z; acc[1][3] += a.y * b.w;
            acc[2][0] += a.z * b.x; acc[2][1] += a.z * b.y; acc[2][2] += a.z * b.z; acc[2][3] += a.z * b.w;
            acc[3][0] += a.w * b.x; acc[3][1] += a.w * b.y; acc[3][2] += a.w * b.z; acc[3][3] += a.w * b.w;
        }
        __syncthreads();
    }

    #pragma unroll
    for (int i = 0; i < 4; i++) {
        float4 v = make_float4(acc[i][0], acc[i][1], acc[i][2], acc[i][3]);
        *(float4*)(C + (size_t)(m0 + ty * 4 + i) * N + n0 + tx * 4) = v;
    }
}

// ---------------- per-head RMSNorm + RoPE (in-place on g_q / g_k) -----------
__global__ __launch_bounds__(128) void norm_rope_kernel(
    const float* __restrict__ qw, const float* __restrict__ kw)
{
    int h = blockIdx.x;          // 0..15
    int t = blockIdx.y;          // 0..4095
    int d = threadIdx.x;         // 0..127
    int s = t & (SS - 1);

    float* qp = g_q + (size_t)t * NF + h * HD;
    float* kp = g_k + (size_t)t * NF + h * HD;
    float q = qp[d];
    float k = kp[d];

    float sq = q * q, sk = k * k;
    #pragma unroll
    for (int m = 16; m; m >>= 1) {
        sq += __shfl_xor_sync(0xffffffffu, sq, m);
        sk += __shfl_xor_sync(0xffffffffu, sk, m);
    }
    __shared__ float rq[4], rk[4];
    __shared__ float shq[HD], shk[HD];
    int wid = d >> 5, lane = d & 31;
    if (lane == 0) { rq[wid] = sq; rk[wid] = sk; }
    __syncthreads();
    float ssq = rq[0] + rq[1] + rq[2] + rq[3];
    float ssk = rk[0] + rk[1] + rk[2] + rk[3];
    float rinvq = rsqrtf(ssq * (1.0f / HD) + 1e-6f);
    float rinvk = rsqrtf(ssk * (1.0f / HD) + 1e-6f);
    float qn = q * rinvq * qw[d];
    float kn = k * rinvk * kw[d];
    shq[d] = qn; shk[d] = kn;
    __syncthreads();

    int f = d & 63;
    float c = g_cos[s * 64 + f];
    float sn = g_sin[s * 64 + f];
    float qo, ko;
    if (d < 64) {
        qo = qn * c - shq[d + 64] * sn;
        ko = kn * c - shk[d + 64] * sn;
    } else {
        qo = qn * c + shq[d - 64] * sn;
        ko = kn * c + shk[d - 64] * sn;
    }
    qp[d] = qo;
    kp[d] = ko;
}

// ---------------- flash attention, fp32, 64q x 64k tiles --------------------
// smem: Qs[128][64] (transposed), Ks[128][64] (transposed), Vs[64][128], Ps[64][65]
#define SM_QS 0
#define SM_KS (128 * 64)
#define SM_VS (SM_KS + 128 * 64)
#define SM_PS (SM_VS + 64 * 128)
#define SM_TOTAL_F (SM_PS + 64 * 65)

__global__ __launch_bounds__(256, 1) void attn_kernel(
    const float* __restrict__ Q, const float* __restrict__ K,
    const float* __restrict__ V, const float* __restrict__ mask,
    float* __restrict__ O)
{
    extern __shared__ float sm[];
    float* Qs = sm + SM_QS;
    float* Ks = sm + SM_KS;
    float* Vs = sm + SM_VS;
    float* Ps = sm + SM_PS;

    int tid = threadIdx.x;
    int tx = tid & 15, ty = tid >> 4;
    int q0 = blockIdx.x * 64;
    int bh = blockIdx.y;
    int b = bh >> 4, h = bh & 15;

    const float* Qb = Q + (size_t)b * SS * NF + (size_t)h * HD;
    const float* Kb = K + (size_t)b * SS * NF + (size_t)h * HD;
    const float* Vb = V + (size_t)b * SS * NF + (size_t)h * HD;
    const float* Mb = mask + (size_t)b * SS * SS;

    // load Q tile transposed: Qs[k][row]
    for (int idx = tid; idx < 64 * 32; idx += 256) {
        int r = idx >> 5, c4 = (idx & 31) << 2;
        float4 v = *(const float4*)(Qb + (size_t)(q0 + r) * NF + c4);
        Qs[(c4 + 0) * 64 + r] = v.x; Qs[(c4 + 1) * 64 + r] = v.y;
        Qs[(c4 + 2) * 64 + r] = v.z; Qs[(c4 + 3) * 64 + r] = v.w;
    }

    float o[4][8];
    float mrow[4], lrow[4];
    #pragma unroll
    for (int i = 0; i < 4; i++) {
        mrow[i] = -1e30f; lrow[i] = 0.f;
        #pragma unroll
        for (int j = 0; j < 8; j++) o[i][j] = 0.f;
    }
    const float scale = 0.08838834764831845f;

    for (int k0 = 0; k0 < SS; k0 += 64) {
        __syncthreads();   // protect Ks/Vs/Ps (and first-iter Q load)
        for (int idx = tid; idx < 64 * 32; idx += 256) {
            int r = idx >> 5, c4 = (idx & 31) << 2;
            float4 kv = *(const float4*)(Kb + (size_t)(k0 + r) * NF + c4);
            Ks[(c4 + 0) * 64 + r] = kv.x; Ks[(c4 + 1) * 64 + r] = kv.y;
            Ks[(c4 + 2) * 64 + r] = kv.z; Ks[(c4 + 3) * 64 + r] = kv.w;
            float4 vv = *(const float4*)(Vb + (size_t)(k0 + r) * NF + c4);
            *(float4*)(&Vs[r * 128 + c4]) = vv;
        }
        __syncthreads();

        // S = Q * K^T  (64x64, K-dim 128)
        float s[4][4] = {};
        #pragma unroll 8
        for (int kk = 0; kk < 128; kk++) {
            float4 a = *(const float4*)(Qs + kk * 64 + ty * 4);
            float4 b4 = *(const float4*)(Ks + kk * 64 + tx * 4);
            s[0][0] += a.x * b4.x; s[0][1] += a.x * b4.y; s[0][2] += a.x * b4.z; s[0][3] += a.x * b4.w;
            s[1][0] += a.y * b4.x; s[1][1] += a.y * b4.y; s[1][2] += a.y * b4.z; s[1][3] += a.y * b4.w;
            s[2][0] += a.z * b4.x; s[2][1] += a.z * b4.y; s[2][2] += a.z * b4.z; s[2][3] += a.z * b4.w;
            s[3][0] += a.w * b4.x; s[3][1] += a.w * b4.y; s[3][2] += a.w * b4.z; s[3][3] += a.w * b4.w;
        }

        // scale + additive mask
        #pragma unroll
        for (int i = 0; i < 4; i++) {
            const float* mr = Mb + (size_t)(q0 + ty * 4 + i) * SS + k0 + tx * 4;
            #pragma unroll
            for (int j = 0; j < 4; j++)
                s[i][j] = s[i][j] * scale + mr[j];
        }

        // online softmax update
        #pragma unroll
        for (int i = 0; i < 4; i++) {
            float mx = fmaxf(fmaxf(s[i][0], s[i][1]), fmaxf(s[i][2], s[i][3]));
            #pragma unroll
            for (int m = 8; m; m >>= 1)
                mx = fmaxf(mx, __shfl_xor_sync(0xffffffffu, mx, m));
            float mnew = fmaxf(mrow[i], mx);
            float factor = __expf(mrow[i] - mnew);
            float psum = 0.f;
            int row = ty * 4 + i;
            #pragma unroll
            for (int j = 0; j < 4; j++) {
                float p = __expf(s[i][j] - mnew);
                Ps[row * 65 + tx * 4 + j] = p;
                psum += p;
            }
            #pragma unroll
            for (int m = 8; m; m >>= 1)
                psum += __shfl_xor_sync(0xffffffffu, psum, m);
            lrow[i] = lrow[i] * factor + psum;
            mrow[i] = mnew;
            #pragma unroll
            for (int j = 0; j < 8; j++) o[i][j] *= factor;
        }
        __syncthreads();

        // O += P * V   (64x128, K-dim 64)
        #pragma unroll 4
        for (int kk = 0; kk < 64; kk++) {
            float p0 = Ps[(ty * 4 + 0) * 65 + kk];
            float p1 = Ps[(ty * 4 + 1) * 65 + kk];
            float p2 = Ps[(ty * 4 + 2) * 65 + kk];
            float p3 = Ps[(ty * 4 + 3) * 65 + kk];
            float4 v0 = *(const float4*)(Vs + kk * 128 + tx * 8);
            float4 v1 = *(const float4*)(Vs + kk * 128 + tx * 8 + 4);
            o[0][0] += p0 * v0.x; o[0][1] += p0 * v0.y; o[0][2] += p0 * v0.z; o[0][3] += p0 * v0.w;
            o[0][4] += p0 * v1.x; o[0][5] += p0 * v1.y; o[0][6] += p0 * v1.z; o[0][7] += p0 * v1.w;
            o[1][0] += p1 * v0.x; o[1][1] += p1 * v0.y; o[1][2] += p1 * v0.z; o[1][3] += p1 * v0.w;
            o[1][4] += p1 * v1.x; o[1][5] += p1 * v1.y; o[1][6] += p1 * v1.z; o[1][7] += p1 * v1.w;
            o[2][0] += p2 * v0.x; o[2][1] += p2 * v0.y; o[2][2] += p2 * v0.z; o[2][3] += p2 * v0.w;
            o[2][4] += p2 * v1.x; o[2][5] += p2 * v1.y; o[2][6] += p2 * v1.z; o[2][7] += p2 * v1.w;
            o[3][0] += p3 * v0.x; o[3][1] += p3 * v0.y; o[3][2] += p3 * v0.z; o[3][3] += p3 * v0.w;
            o[3][4] += p3 * v1.x; o[3][5] += p3 * v1.y; o[3][6] += p3 * v1.z; o[3][7] += p3 * v1.w;
        }
    }

    // epilogue: normalize and write token-major
    #pragma unroll
    for (int i = 0; i < 4; i++) {
        float inv = 1.0f / lrow[i];
        int row = q0 + ty * 4 + i;
        float4 w0 = make_float4(o[i][0] * inv, o[i][1] * inv, o[i][2] * inv, o[i][3] * inv);
        float4 w1 = make_float4(o[i][4] * inv, o[i][5] * inv, o[i][6] * inv, o[i][7] * inv);
        float* op = O + (size_t)(b * SS + row) * NF + h * HD + tx * 8;
        *(float4*)(op) = w0;
        *(float4*)(op + 4) = w1;
    }
}

// ---------------- launch ----------------------------------------------------
extern "C" void kernel_launch(void* const* d_in, const int* in_sizes, int n_in,
                              void* d_out, int out_size) {
    const float* x     = (const float*)d_in[0];
    const float* mask0 = (const float*)d_in[1];
    const float* wq    = (const float*)d_in[2];
    const float* wk    = (const float*)d_in[3];
    const float* wv    = (const float*)d_in[4];
    const float* wo    = (const float*)d_in[5];
    const float* qnw   = (const float*)d_in[6];
    const float* knw   = (const float*)d_in[7];
    float* out = (float*)d_out;

    float *pq, *pk, *pv, *pa;
    cudaGetSymbolAddress((void**)&pq, g_q);
    cudaGetSymbolAddress((void**)&pk, g_k);
    cudaGetSymbolAddress((void**)&pv, g_v);
    cudaGetSymbolAddress((void**)&pa, g_a);

    static bool attr_set = false;
    if (!attr_set) {
        cudaFuncSetAttribute(attn_kernel, cudaFuncAttributeMaxDynamicSharedMemorySize,
                             SM_TOTAL_F * sizeof(float));
        attr_set = true;
    }

    // 1. RoPE tables
    rope_table_kernel<<<(SS * 64 + 255) / 256, 256>>>();

    // 2. QKV projections: [4096,192] x [2048,192]^T, 3 outputs via grid.z
    gemm_nt_kernel<<<dim3(NT / BM, NF / BN, 3), 256>>>(
        x, wq, wk, wv, pq, pk, pv, NT, NF, DD);

    // 3. per-head RMSNorm + RoPE on Q,K (in place)
    norm_rope_kernel<<<dim3(HH, NT), 128>>>(qnw, knw);

    // 4. attention
    attn_kernel<<<dim3(SS / 64, BB * HH), 256, SM_TOTAL_F * sizeof(float)>>>(
        pq, pk, pv, mask0, pa);

    // 5. output projection: [4096,2048] x [192,2048]^T -> d_out [4096,192]
    gemm_nt_kernel<<<dim3(NT / BM, DD / BN, 1), 256>>>(
        pa, wo, wo, wo, out, out, out, NT, DD, NF);
}

// round 3
// speedup vs baseline: 2.6354x; 2.6354x over previous
#include <cuda_runtime.h>
#include <cuda_bf16.h>
#include <math.h>
#include <stdint.h>

// Problem dims (fixed by reference)
#define BB 2
#define SS 2048
#define DD 192
#define HH 16
#define HD 128
#define NT (BB*SS)        // 4096 tokens
#define NF (HH*HD)        // 2048 features

// ---------------- scratch (device globals; no allocations allowed) ----------
__device__ float g_q[NT * NF];     // token-major [t][h*128+d]
__device__ float g_k[NT * NF];
__device__ float g_v[NT * NF];
__device__ float g_a[NT * NF];     // attention output, token-major
__device__ float g_cos[SS * 64];
__device__ float g_sin[SS * 64];

// =======================  warp-MMA helpers (generic PTX, sm_80+) ============
__device__ __forceinline__ uint32_t smem_u32(const void* p) {
    uint32_t a;
    asm("{ .reg .u64 t; cvta.to.shared.u64 t, %1; cvt.u32.u64 %0, t; }"
        : "=r"(a) : "l"(p));
    return a;
}

__device__ __forceinline__ void ldsm4(uint32_t* r, uint32_t addr) {
    asm volatile("ldmatrix.sync.aligned.m8n8.x4.shared.b16 {%0,%1,%2,%3}, [%4];"
        : "=r"(r[0]), "=r"(r[1]), "=r"(r[2]), "=r"(r[3]) : "r"(addr) : "memory");
}
__device__ __forceinline__ void ldsm4t(uint32_t* r, uint32_t addr) {
    asm volatile("ldmatrix.sync.aligned.m8n8.x4.trans.shared.b16 {%0,%1,%2,%3}, [%4];"
        : "=r"(r[0]), "=r"(r[1]), "=r"(r[2]), "=r"(r[3]) : "r"(addr) : "memory");
}

// D(m16n8) += A(m16k16,row) * B(k16n8,col), bf16 in, fp32 accum
__device__ __forceinline__ void mma16816(float* c, const uint32_t* a, uint32_t b0, uint32_t b1) {
    asm volatile(
        "mma.sync.aligned.m16n8k16.row.col.f32.bf16.bf16.f32 "
        "{%0,%1,%2,%3}, {%4,%5,%6,%7}, {%8,%9}, {%0,%1,%2,%3};"
        : "+f"(c[0]), "+f"(c[1]), "+f"(c[2]), "+f"(c[3])
        : "r"(a[0]), "r"(a[1]), "r"(a[2]), "r"(a[3]), "r"(b0), "r"(b1));
}

__device__ __forceinline__ uint32_t pack_bf16(float a, float b) {
    __nv_bfloat162 t = __floats2bfloat162_rn(a, b);
    return *(uint32_t*)&t;
}
__device__ __forceinline__ void split1(float x, float& hi, float& lo) {
    hi = __bfloat162float(__float2bfloat16(x));
    lo = x - hi;
}

// XOR swizzle at 16B granularity. 256B rows (16 chunks) and 128B rows (8 chunks).
__device__ __forceinline__ uint32_t swz256(int row, int colb) {
    return (uint32_t)(row * 256 + ((((colb >> 4) ^ (row & 7)) << 4) | (colb & 15)));
}
__device__ __forceinline__ uint32_t swz128(int row, int colb) {
    return (uint32_t)(row * 128 + (((((colb >> 4) ^ (row & 7)) & 7) << 4) | (colb & 15)));
}

// ---------------- RoPE table (fp64-accurate) --------------------------------
__global__ void rope_table_kernel() {
    int i = blockIdx.x * blockDim.x + threadIdx.x;
    if (i >= SS * 64) return;
    int s = i >> 6, f = i & 63;
    double e = ((double)(2 * f) / 128.0) * 13.815510557964274;
    double invf = exp(-e);
    double ph = (double)s * invf;
    g_cos[i] = (float)cos(ph);
    g_sin[i] = (float)sin(ph);
}

// ---------------- Tiled SGEMM: C[M][N] = A[M][K] * W[N][K]^T ----------------
#define BM 64
#define BN 64
#define BK 16

__global__ __launch_bounds__(256) void gemm_nt_kernel(
    const float* __restrict__ A,
    const float* __restrict__ W0, const float* __restrict__ W1, const float* __restrict__ W2,
    float* __restrict__ C0, float* __restrict__ C1, float* __restrict__ C2,
    int M, int N, int K)
{
    const float* __restrict__ W = (blockIdx.z == 0) ? W0 : (blockIdx.z == 1) ? W1 : W2;
    float* __restrict__ C = (blockIdx.z == 0) ? C0 : (blockIdx.z == 1) ? C1 : C2;

    __shared__ float As[BK][BM];
    __shared__ float Bs[BK][BN];

    int tid = threadIdx.x;
    int tx = tid & 15, ty = tid >> 4;
    int m0 = blockIdx.x * BM;
    int n0 = blockIdx.y * BN;

    int lr = tid >> 2;
    int lc = (tid & 3) << 2;

    float acc[4][4] = {};

    for (int k0 = 0; k0 < K; k0 += BK) {
        float4 av = *(const float4*)(A + (size_t)(m0 + lr) * K + k0 + lc);
        As[lc + 0][lr] = av.x; As[lc + 1][lr] = av.y;
        As[lc + 2][lr] = av.z; As[lc + 3][lr] = av.w;
        float4 bv = *(const float4*)(W + (size_t)(n0 + lr) * K + k0 + lc);
        Bs[lc + 0][lr] = bv.x; Bs[lc + 1][lr] = bv.y;
        Bs[lc + 2][lr] = bv.z; Bs[lc + 3][lr] = bv.w;
        __syncthreads();

        #pragma unroll
        for (int kk = 0; kk < BK; kk++) {
            float4 a = *(const float4*)(&As[kk][ty * 4]);
            float4 b = *(const float4*)(&Bs[kk][tx * 4]);
            acc[0][0] += a.x * b.x; acc[0][1] += a.x * b.y; acc[0][2] += a.x * b.z; acc[0][3] += a.x * b.w;
            acc[1][0] += a.y * b.x; acc[1][1] += a.y * b.y; acc[1][2] += a.y * b.z; acc[1][3] += a.y * b.w;
            acc[2][0] += a.z * b.x; acc[2][1] += a.z * b.y; acc[2][2] += a.z * b.z; acc[2][3] += a.z * b.w;
            acc[3][0] += a.w * b.x; acc[3][1] += a.w * b.y; acc[3][2] += a.w * b.z; acc[3][3] += a.w * b.w;
        }
        __syncthreads();
    }

    #pragma unroll
    for (int i = 0; i < 4; i++) {
        float4 v = make_float4(acc[i][0], acc[i][1], acc[i][2], acc[i][3]);
        *(float4*)(C + (size_t)(m0 + ty * 4 + i) * N + n0 + tx * 4) = v;
    }
}

// ---------------- per-head RMSNorm + RoPE (in-place on g_q / g_k) -----------
__global__ __launch_bounds__(128) void norm_rope_kernel(
    const float* __restrict__ qw, const float* __restrict__ kw)
{
    int h = blockIdx.x;
    int t = blockIdx.y;
    int d = threadIdx.x;
    int s = t & (SS - 1);

    float* qp = g_q + (size_t)t * NF + h * HD;
    float* kp = g_k + (size_t)t * NF + h * HD;
    float q = qp[d];
    float k = kp[d];

    float sq = q * q, sk = k * k;
    #pragma unroll
    for (int m = 16; m; m >>= 1) {
        sq += __shfl_xor_sync(0xffffffffu, sq, m);
        sk += __shfl_xor_sync(0xffffffffu, sk, m);
    }
    __shared__ float rq[4], rk[4];
    __shared__ float shq[HD], shk[HD];
    int wid = d >> 5, lane = d & 31;
    if (lane == 0) { rq[wid] = sq; rk[wid] = sk; }
    __syncthreads();
    float ssq = rq[0] + rq[1] + rq[2] + rq[3];
    float ssk = rk[0] + rk[1] + rk[2] + rk[3];
    float rinvq = rsqrtf(ssq * (1.0f / HD) + 1e-6f);
    float rinvk = rsqrtf(ssk * (1.0f / HD) + 1e-6f);
    float qn = q * rinvq * qw[d];
    float kn = k * rinvk * kw[d];
    shq[d] = qn; shk[d] = kn;
    __syncthreads();

    int f = d & 63;
    float c = g_cos[s * 64 + f];
    float sn = g_sin[s * 64 + f];
    float qo, ko;
    if (d < 64) {
        qo = qn * c - shq[d + 64] * sn;
        ko = kn * c - shk[d + 64] * sn;
    } else {
        qo = qn * c + shq[d - 64] * sn;
        ko = kn * c + shk[d - 64] * sn;
    }
    qp[d] = qo;
    kp[d] = ko;
}

// ========== mma.sync flash attention, split-bf16 (3-term), Br=128, Bc=64 ====
// smem byte offsets
#define SM_QH 0
#define SM_QL 32768
#define SM_KH 65536
#define SM_KL 81920
#define SM_VH 98304
#define SM_VL 114688
#define SM_PH 131072
#define SM_PL 147456
#define SM_ATT_TOTAL 163840

__global__ __launch_bounds__(256, 1) void attn_mma_kernel(
    const float* __restrict__ Q, const float* __restrict__ K,
    const float* __restrict__ V, const float* __restrict__ mask,
    float* __restrict__ O)
{
    extern __shared__ char smc[];
    uint32_t smb = smem_u32(smc);
    const uint32_t QHb = smb + SM_QH, QLb = smb + SM_QL;
    const uint32_t KHb = smb + SM_KH, KLb = smb + SM_KL;
    const uint32_t VHb = smb + SM_VH, VLb = smb + SM_VL;
    const uint32_t PHb = smb + SM_PH, PLb = smb + SM_PL;

    int tid = threadIdx.x;
    int w = tid >> 5, lane = tid & 31;
    int w16 = w * 16;
    int g = lane >> 2, tig = lane & 3;
    int tlane = lane >> 3, ri = lane & 7;   // ldmatrix tile id / row-in-tile

    int q0 = blockIdx.x * 128;
    int bh = blockIdx.y;
    int b = bh >> 4, h = bh & 15;

    const float* Qb = Q + (size_t)(b * SS) * NF + h * HD;
    const float* Kb = K + (size_t)(b * SS) * NF + h * HD;
    const float* Vb = V + (size_t)(b * SS) * NF + h * HD;
    const float* Mb = mask + (size_t)b * SS * SS;

    // ---- stage Q tile (128 x 128) as split bf16, swizzled ----
    for (int idx = tid; idx < 128 * 32; idx += 256) {
        int r = idx >> 5, c4 = (idx & 31) << 2;
        float4 qv = *(const float4*)(Qb + (size_t)(q0 + r) * NF + c4);
        float hx, lx, hy, ly, hz, lz, hw, lw;
        split1(qv.x, hx, lx); split1(qv.y, hy, ly);
        split1(qv.z, hz, lz); split1(qv.w, hw, lw);
        uint32_t off = swz256(r, c4 * 2);
        uint2 ph2; ph2.x = pack_bf16(hx, hy); ph2.y = pack_bf16(hz, hw);
        uint2 pl2; pl2.x = pack_bf16(lx, ly); pl2.y = pack_bf16(lz, lw);
        *(uint2*)(smc + SM_QH + off) = ph2;
        *(uint2*)(smc + SM_QL + off) = pl2;
    }

    float o[16][4];
    #pragma unroll
    for (int j = 0; j < 16; j++) { o[j][0] = o[j][1] = o[j][2] = o[j][3] = 0.f; }
    float m_0 = -INFINITY, m_1 = -INFINITY, l_0 = 0.f, l_1 = 0.f;
    const float scale = 0.08838834764831845f;

    // ldmatrix address components (constant per thread)
    int arow = w16 + (tlane & 1) * 8 + ri;           // A-frag row (Q and P)
    int acol_half = (tlane >> 1) * 16;               // A-frag k-half byte offset
    int brow_in = (tlane >> 1) * 8 + ri;             // B-frag (K) row within 16-row pair
    int bcol_half = (tlane & 1) * 16;                // B-frag k-half byte offset
    int vrow_in = (tlane & 1) * 8 + ri;              // V trans: kv row within 16
    int vcol_half = (tlane >> 1) * 16;               // V trans: hd-half byte offset

    for (int it = 0; it < 32; it++) {
        int k0 = it * 64;
        __syncthreads();   // previous iter's K/V reads done (and Q staged, iter 0)

        // ---- stage K, V tiles (64 x 128) as split bf16, swizzled ----
        for (int idx = tid; idx < 64 * 32; idx += 256) {
            int r = idx >> 5, c4 = (idx & 31) << 2;
            uint32_t off = swz256(r, c4 * 2);
            float4 kv = *(const float4*)(Kb + (size_t)(k0 + r) * NF + c4);
            float hx, lx, hy, ly, hz, lz, hw, lw;
            split1(kv.x, hx, lx); split1(kv.y, hy, ly);
            split1(kv.z, hz, lz); split1(kv.w, hw, lw);
            uint2 kh2; kh2.x = pack_bf16(hx, hy); kh2.y = pack_bf16(hz, hw);
            uint2 kl2; kl2.x = pack_bf16(lx, ly); kl2.y = pack_bf16(lz, lw);
            *(uint2*)(smc + SM_KH + off) = kh2;
            *(uint2*)(smc + SM_KL + off) = kl2;

            float4 vv = *(const float4*)(Vb + (size_t)(k0 + r) * NF + c4);
            split1(vv.x, hx, lx); split1(vv.y, hy, ly);
            split1(vv.z, hz, lz); split1(vv.w, hw, lw);
            uint2 vh2; vh2.x = pack_bf16(hx, hy); vh2.y = pack_bf16(hz, hw);
            uint2 vl2; vl2.x = pack_bf16(lx, ly); vl2.y = pack_bf16(lz, lw);
            *(uint2*)(smc + SM_VH + off) = vh2;
            *(uint2*)(smc + SM_VL + off) = vl2;
        }
        __syncthreads();

        // ---- S = Q K^T (3-term split), warp covers 16 rows x 64 cols ----
        float s[8][4];
        #pragma unroll
        for (int j = 0; j < 8; j++) { s[j][0] = s[j][1] = s[j][2] = s[j][3] = 0.f; }

        #pragma unroll
        for (int ks = 0; ks < 8; ks++) {
            uint32_t aH[4], aL[4];
            uint32_t qoff = swz256(arow, ks * 32 + acol_half);
            ldsm4(aH, QHb + qoff);
            ldsm4(aL, QLb + qoff);
            uint32_t bHf[16], bLf[16];
            #pragma unroll
            for (int p = 0; p < 4; p++) {
                uint32_t koff = swz256(p * 16 + brow_in, ks * 32 + bcol_half);
                ldsm4(bHf + p * 4, KHb + koff);
                ldsm4(bLf + p * 4, KLb + koff);
            }
            #pragma unroll
            for (int j = 0; j < 8; j++) {
                uint32_t b0h = bHf[(j >> 1) * 4 + (j & 1) * 2], b1h = bHf[(j >> 1) * 4 + (j & 1) * 2 + 1];
                uint32_t b0l = bLf[(j >> 1) * 4 + (j & 1) * 2], b1l = bLf[(j >> 1) * 4 + (j & 1) * 2 + 1];
                mma16816(s[j], aH, b0h, b1h);
                mma16816(s[j], aL, b0h, b1h);
                mma16816(s[j], aH, b0l, b1l);
            }
        }

        // ---- online softmax (warp-local; rows g and g+8 of this warp) ----
        const float* mr0 = Mb + (size_t)(q0 + w16 + g) * SS + k0;
        const float* mr1 = mr0 + (size_t)8 * SS;
        float mx0 = -INFINITY, mx1 = -INFINITY;
        #pragma unroll
        for (int j = 0; j < 8; j++) {
            float2 mk0 = *(const float2*)(mr0 + j * 8 + tig * 2);
            float2 mk1 = *(const float2*)(mr1 + j * 8 + tig * 2);
            s[j][0] = fmaf(s[j][0], scale, mk0.x);
            s[j][1] = fmaf(s[j][1], scale, mk0.y);
            s[j][2] = fmaf(s[j][2], scale, mk1.x);
            s[j][3] = fmaf(s[j][3], scale, mk1.y);
            mx0 = fmaxf(mx0, fmaxf(s[j][0], s[j][1]));
            mx1 = fmaxf(mx1, fmaxf(s[j][2], s[j][3]));
        }
        mx0 = fmaxf(mx0, __shfl_xor_sync(0xffffffffu, mx0, 1));
        mx0 = fmaxf(mx0, __shfl_xor_sync(0xffffffffu, mx0, 2));
        mx1 = fmaxf(mx1, __shfl_xor_sync(0xffffffffu, mx1, 1));
        mx1 = fmaxf(mx1, __shfl_xor_sync(0xffffffffu, mx1, 2));
        float mn0 = fmaxf(m_0, mx0), mn1 = fmaxf(m_1, mx1);
        float f0 = __expf(m_0 - mn0), f1 = __expf(m_1 - mn1);

        float sum0 = 0.f, sum1 = 0.f;
        #pragma unroll
        for (int j = 0; j < 8; j++) {
            float p00 = __expf(s[j][0] - mn0);
            float p01 = __expf(s[j][1] - mn0);
            float p10 = __expf(s[j][2] - mn1);
            float p11 = __expf(s[j][3] - mn1);
            sum0 += p00 + p01; sum1 += p10 + p11;
            float h00, l00, h01, l01, h10, l10, h11, l11;
            split1(p00, h00, l00); split1(p01, h01, l01);
            split1(p10, h10, l10); split1(p11, h11, l11);
            uint32_t off0 = swz128(w16 + g, j * 16 + tig * 4);
            uint32_t off1 = swz128(w16 + g + 8, j * 16 + tig * 4);
            *(uint32_t*)(smc + SM_PH + off0) = pack_bf16(h00, h01);
            *(uint32_t*)(smc + SM_PL + off0) = pack_bf16(l00, l01);
            *(uint32_t*)(smc + SM_PH + off1) = pack_bf16(h10, h11);
            *(uint32_t*)(smc + SM_PL + off1) = pack_bf16(l10, l11);
        }
        sum0 += __shfl_xor_sync(0xffffffffu, sum0, 1);
        sum0 += __shfl_xor_sync(0xffffffffu, sum0, 2);
        sum1 += __shfl_xor_sync(0xffffffffu, sum1, 1);
        sum1 += __shfl_xor_sync(0xffffffffu, sum1, 2);
        l_0 = l_0 * f0 + sum0; l_1 = l_1 * f1 + sum1;
        m_0 = mn0; m_1 = mn1;

        #pragma unroll
        for (int j = 0; j < 16; j++) {
            o[j][0] *= f0; o[j][1] *= f0;
            o[j][2] *= f1; o[j][3] *= f1;
        }
        __syncwarp();   // P visible to own warp's ldmatrix

        // ---- O += P V (3-term split), 16 rows x 128 cols, kdim 64 ----
        #pragma unroll
        for (int ks = 0; ks < 4; ks++) {
            uint32_t aH[4], aL[4];
            uint32_t poff = swz128(arow, ks * 32 + acol_half);
            ldsm4(aH, PHb + poff);
            ldsm4(aL, PLb + poff);
            #pragma unroll
            for (int p = 0; p < 8; p++) {
                uint32_t vH[4], vL[4];
                uint32_t voff = swz256(ks * 16 + vrow_in, p * 32 + vcol_half);
                ldsm4t(vH, VHb + voff);
                ldsm4t(vL, VLb + voff);
                int j0 = p * 2, j1 = p * 2 + 1;
                mma16816(o[j0], aH, vH[0], vH[1]);
                mma16816(o[j1], aH, vH[2], vH[3]);
                mma16816(o[j0], aL, vH[0], vH[1]);
                mma16816(o[j1], aL, vH[2], vH[3]);
                mma16816(o[j0], aH, vL[0], vL[1]);
                mma16816(o[j1], aH, vL[2], vL[3]);
            }
        }
    }

    // ---- epilogue: O / l -> gmem (token-major) ----
    float inv0 = 1.0f / l_0, inv1 = 1.0f / l_1;
    float* op0 = O + (size_t)(b * SS + q0 + w16 + g) * NF + h * HD;
    float* op1 = op0 + (size_t)8 * NF;
    #pragma unroll
    for (int j = 0; j < 16; j++) {
        *(float2*)(op0 + j * 8 + tig * 2) = make_float2(o[j][0] * inv0, o[j][1] * inv0);
        *(float2*)(op1 + j * 8 + tig * 2) = make_float2(o[j][2] * inv1, o[j][3] * inv1);
    }
}

// ---------------- launch ----------------------------------------------------
extern "C" void kernel_launch(void* const* d_in, const int* in_sizes, int n_in,
                              void* d_out, int out_size) {
    const float* x     = (const float*)d_in[0];
    const float* mask0 = (const float*)d_in[1];
    const float* wq    = (const float*)d_in[2];
    const float* wk    = (const float*)d_in[3];
    const float* wv    = (const float*)d_in[4];
    const float* wo    = (const float*)d_in[5];
    const float* qnw   = (const float*)d_in[6];
    const float* knw   = (const float*)d_in[7];
    float* out = (float*)d_out;

    float *pq, *pk, *pv, *pa;
    cudaGetSymbolAddress((void**)&pq, g_q);
    cudaGetSymbolAddress((void**)&pk, g_k);
    cudaGetSymbolAddress((void**)&pv, g_v);
    cudaGetSymbolAddress((void**)&pa, g_a);

    static bool attr_set = false;
    if (!attr_set) {
        cudaFuncSetAttribute(attn_mma_kernel, cudaFuncAttributeMaxDynamicSharedMemorySize,
                             SM_ATT_TOTAL);
        attr_set = true;
    }

    // 1. RoPE tables
    rope_table_kernel<<<(SS * 64 + 255) / 256, 256>>>();

    // 2. QKV projections
    gemm_nt_kernel<<<dim3(NT / BM, NF / BN, 3), 256>>>(
        x, wq, wk, wv, pq, pk, pv, NT, NF, DD);

    // 3. per-head RMSNorm + RoPE on Q,K
    norm_rope_kernel<<<dim3(HH, NT), 128>>>(qnw, knw);

    // 4. attention (mma.sync bf16 split)
    attn_mma_kernel<<<dim3(SS / 128, BB * HH), 256, SM_ATT_TOTAL>>>(
        pq, pk, pv, mask0, pa);

    // 5. output projection
    gemm_nt_kernel<<<dim3(NT / BM, DD / BN, 1), 256>>>(
        pa, wo, wo, wo, out, out, out, NT, DD, NF);
}

// round 4
// speedup vs baseline: 3.0261x; 1.1482x over previous
#include <cuda_runtime.h>
#include <cuda_bf16.h>
#include <math.h>
#include <stdint.h>

// Problem dims (fixed by reference)
#define BB 2
#define SS 2048
#define DD 192
#define HH 16
#define HD 128
#define NT (BB*SS)        // 4096 tokens
#define NF (HH*HD)        // 2048 features

// ---------------- scratch (device globals; no allocations allowed) ----------
__device__ float g_q[NT * NF];     // fp32 projection outputs (scratch)
__device__ float g_k[NT * NF];
__device__ float g_v[NT * NF];
__device__ float g_a[NT * NF];     // attention output, token-major
__device__ float g_cos[SS * 64];
__device__ float g_sin[SS * 64];

// pre-swizzled split-bf16 planes: [(b*HH+h)][s][256B row, 16B-chunk XOR (s&7)]
#define PLANE_BYTES ((size_t)NT * NF * 2)
__device__ __align__(1024) unsigned char g_pqh[PLANE_BYTES];
__device__ __align__(1024) unsigned char g_pql[PLANE_BYTES];
__device__ __align__(1024) unsigned char g_pkh[PLANE_BYTES];
__device__ __align__(1024) unsigned char g_pkl[PLANE_BYTES];
__device__ __align__(1024) unsigned char g_pvh[PLANE_BYTES];
__device__ __align__(1024) unsigned char g_pvl[PLANE_BYTES];

// plane byte offset for (bh, s, d)
__device__ __forceinline__ size_t plane_off(int bh, int s, int d) {
    int colb = d * 2;
    int sw = ((((colb >> 4) ^ (s & 7)) << 4) | (colb & 15));
    return ((size_t)bh * SS + s) * 256 + sw;
}

// =======================  warp-MMA helpers (generic PTX, sm_80+) ============
__device__ __forceinline__ uint32_t smem_u32(const void* p) {
    uint32_t a;
    asm("{ .reg .u64 t; cvta.to.shared.u64 t, %1; cvt.u32.u64 %0, t; }"
        : "=r"(a) : "l"(p));
    return a;
}

__device__ __forceinline__ void ldsm4(uint32_t* r, uint32_t addr) {
    asm volatile("ldmatrix.sync.aligned.m8n8.x4.shared.b16 {%0,%1,%2,%3}, [%4];"
        : "=r"(r[0]), "=r"(r[1]), "=r"(r[2]), "=r"(r[3]) : "r"(addr) : "memory");
}
__device__ __forceinline__ void ldsm4t(uint32_t* r, uint32_t addr) {
    asm volatile("ldmatrix.sync.aligned.m8n8.x4.trans.shared.b16 {%0,%1,%2,%3}, [%4];"
        : "=r"(r[0]), "=r"(r[1]), "=r"(r[2]), "=r"(r[3]) : "r"(addr) : "memory");
}

__device__ __forceinline__ void mma16816(float* c, const uint32_t* a, uint32_t b0, uint32_t b1) {
    asm volatile(
        "mma.sync.aligned.m16n8k16.row.col.f32.bf16.bf16.f32 "
        "{%0,%1,%2,%3}, {%4,%5,%6,%7}, {%8,%9}, {%0,%1,%2,%3};"
        : "+f"(c[0]), "+f"(c[1]), "+f"(c[2]), "+f"(c[3])
        : "r"(a[0]), "r"(a[1]), "r"(a[2]), "r"(a[3]), "r"(b0), "r"(b1));
}

__device__ __forceinline__ void cp16(uint32_t smem_dst, const void* gsrc) {
    asm volatile("cp.async.cg.shared.global [%0], [%1], 16;"
        :: "r"(smem_dst), "l"(gsrc) : "memory");
}
#define CP_COMMIT() asm volatile("cp.async.commit_group;" ::: "memory")
#define CP_WAIT1()  asm volatile("cp.async.wait_group 1;" ::: "memory")

__device__ __forceinline__ uint32_t pack_bf16(float a, float b) {
    __nv_bfloat162 t = __floats2bfloat162_rn(a, b);
    return *(uint32_t*)&t;
}
__device__ __forceinline__ void split1(float x, float& hi, float& lo) {
    hi = __bfloat162float(__float2bfloat16(x));
    lo = x - hi;
}

// XOR swizzle at 16B granularity (row stride 256B / 128B)
__device__ __forceinline__ uint32_t swz256(int row, int colb) {
    return (uint32_t)(row * 256 + ((((colb >> 4) ^ (row & 7)) << 4) | (colb & 15)));
}
__device__ __forceinline__ uint32_t swz128(int row, int colb) {
    return (uint32_t)(row * 128 + (((((colb >> 4) ^ (row & 7)) & 7) << 4) | (colb & 15)));
}

// ---------------- RoPE table (fp64-accurate) --------------------------------
__global__ void rope_table_kernel() {
    int i = blockIdx.x * blockDim.x + threadIdx.x;
    if (i >= SS * 64) return;
    int s = i >> 6, f = i & 63;
    double e = ((double)(2 * f) / 128.0) * 13.815510557964274;
    double invf = exp(-e);
    double ph = (double)s * invf;
    g_cos[i] = (float)cos(ph);
    g_sin[i] = (float)sin(ph);
}

// ---------------- Tiled SGEMM: C[M][N] = A[M][K] * W[N][K]^T ----------------
#define BM 64
#define BN 64
#define BK 16

__global__ __launch_bounds__(256) void gemm_nt_kernel(
    const float* __restrict__ A,
    const float* __restrict__ W0, const float* __restrict__ W1, const float* __restrict__ W2,
    float* __restrict__ C0, float* __restrict__ C1, float* __restrict__ C2,
    int M, int N, int K)
{
    const float* __restrict__ W = (blockIdx.z == 0) ? W0 : (blockIdx.z == 1) ? W1 : W2;
    float* __restrict__ C = (blockIdx.z == 0) ? C0 : (blockIdx.z == 1) ? C1 : C2;

    __shared__ float As[BK][BM];
    __shared__ float Bs[BK][BN];

    int tid = threadIdx.x;
    int tx = tid & 15, ty = tid >> 4;
    int m0 = blockIdx.x * BM;
    int n0 = blockIdx.y * BN;

    int lr = tid >> 2;
    int lc = (tid & 3) << 2;

    float acc[4][4] = {};

    for (int k0 = 0; k0 < K; k0 += BK) {
        float4 av = *(const float4*)(A + (size_t)(m0 + lr) * K + k0 + lc);
        As[lc + 0][lr] = av.x; As[lc + 1][lr] = av.y;
        As[lc + 2][lr] = av.z; As[lc + 3][lr] = av.w;
        float4 bv = *(const float4*)(W + (size_t)(n0 + lr) * K + k0 + lc);
        Bs[lc + 0][lr] = bv.x; Bs[lc + 1][lr] = bv.y;
        Bs[lc + 2][lr] = bv.z; Bs[lc + 3][lr] = bv.w;
        __syncthreads();

        #pragma unroll
        for (int kk = 0; kk < BK; kk++) {
            float4 a = *(const float4*)(&As[kk][ty * 4]);
            float4 b = *(const float4*)(&Bs[kk][tx * 4]);
            acc[0][0] += a.x * b.x; acc[0][1] += a.x * b.y; acc[0][2] += a.x * b.z; acc[0][3] += a.x * b.w;
            acc[1][0] += a.y * b.x; acc[1][1] += a.y * b.y; acc[1][2] += a.y * b.z; acc[1][3] += a.y * b.w;
            acc[2][0] += a.z * b.x; acc[2][1] += a.z * b.y; acc[2][2] += a.z * b.z; acc[2][3] += a.z * b.w;
            acc[3][0] += a.w * b.x; acc[3][1] += a.w * b.y; acc[3][2] += a.w * b.z; acc[3][3] += a.w * b.w;
        }
        __syncthreads();
    }

    #pragma unroll
    for (int i = 0; i < 4; i++) {
        float4 v = make_float4(acc[i][0], acc[i][1], acc[i][2], acc[i][3]);
        *(float4*)(C + (size_t)(m0 + ty * 4 + i) * N + n0 + tx * 4) = v;
    }
}

// ------ per-head RMSNorm + RoPE + split-bf16 plane emit (Q, K, V) -----------
__global__ __launch_bounds__(128) void norm_rope_kernel(
    const float* __restrict__ qw, const float* __restrict__ kw)
{
    int h = blockIdx.x;
    int t = blockIdx.y;
    int d = threadIdx.x;
    int s = t & (SS - 1);
    int b = t >> 11;               // t / SS
    int bh = b * HH + h;

    const float* qp = g_q + (size_t)t * NF + h * HD;
    const float* kp = g_k + (size_t)t * NF + h * HD;
    const float* vp = g_v + (size_t)t * NF + h * HD;
    float q = qp[d];
    float k = kp[d];
    float v = vp[d];

    float sq = q * q, sk = k * k;
    #pragma unroll
    for (int m = 16; m; m >>= 1) {
        sq += __shfl_xor_sync(0xffffffffu, sq, m);
        sk += __shfl_xor_sync(0xffffffffu, sk, m);
    }
    __shared__ float rq[4], rk[4];
    __shared__ float shq[HD], shk[HD];
    int wid = d >> 5, lane = d & 31;
    if (lane == 0) { rq[wid] = sq; rk[wid] = sk; }
    __syncthreads();
    float ssq = rq[0] + rq[1] + rq[2] + rq[3];
    float ssk = rk[0] + rk[1] + rk[2] + rk[3];
    float rinvq = rsqrtf(ssq * (1.0f / HD) + 1e-6f);
    float rinvk = rsqrtf(ssk * (1.0f / HD) + 1e-6f);
    float qn = q * rinvq * qw[d];
    float kn = k * rinvk * kw[d];
    shq[d] = qn; shk[d] = kn;
    __syncthreads();

    int f = d & 63;
    float c = g_cos[s * 64 + f];
    float sn = g_sin[s * 64 + f];
    float qo, ko;
    if (d < 64) {
        qo = qn * c - shq[d + 64] * sn;
        ko = kn * c - shk[d + 64] * sn;
    } else {
        qo = qn * c + shq[d - 64] * sn;
        ko = kn * c + shk[d - 64] * sn;
    }

    size_t po = plane_off(bh, s, d);
    float hi, lo;
    split1(qo, hi, lo);
    *(__nv_bfloat16*)(g_pqh + po) = __float2bfloat16(hi);
    *(__nv_bfloat16*)(g_pql + po) = __float2bfloat16(lo);
    split1(ko, hi, lo);
    *(__nv_bfloat16*)(g_pkh + po) = __float2bfloat16(hi);
    *(__nv_bfloat16*)(g_pkl + po) = __float2bfloat16(lo);
    split1(v, hi, lo);
    *(__nv_bfloat16*)(g_pvh + po) = __float2bfloat16(hi);
    *(__nv_bfloat16*)(g_pvl + po) = __float2bfloat16(lo);
}

// ========== mma.sync flash attention, pipelined cp.async staging ============
// smem byte offsets
#define SM_QH 0
#define SM_QL 32768
#define SM_PH 65536
#define SM_PL 81920
#define SM_STG 98304          // two 64KB stage buffers: {KH,KL,VH,VL} x 16KB
#define SM_ATT_TOTAL (SM_STG + 2 * 65536)   // 229376

__global__ __launch_bounds__(256, 1) void attn_mma_kernel(
    const float* __restrict__ mask, float* __restrict__ O)
{
    extern __shared__ char smc[];
    uint32_t smb = smem_u32(smc);
    const uint32_t QHb = smb + SM_QH, QLb = smb + SM_QL;
    const uint32_t PHb = smb + SM_PH, PLb = smb + SM_PL;

    int tid = threadIdx.x;
    int w = tid >> 5, lane = tid & 31;
    int w16 = w * 16;
    int g = lane >> 2, tig = lane & 3;
    int tlane = lane >> 3, ri = lane & 7;

    int q0 = blockIdx.x * 128;
    int bh = blockIdx.y;
    int b = bh >> 4;

    const float* Mb = mask + (size_t)b * SS * SS;
    size_t bh_base = (size_t)bh * SS * 256;

    // ---- prologue: Q tile copy (group 0), stage(0) (group 1), stage(1) (group 2)
    {
        size_t qbase = bh_base + (size_t)q0 * 256;
        #pragma unroll
        for (int j = 0; j < 8; j++) {
            uint32_t o = j * 4096 + tid * 16;
            cp16(QHb + o, g_pqh + qbase + o);
            cp16(QLb + o, g_pql + qbase + o);
        }
        CP_COMMIT();
    }
    #pragma unroll
    for (int pre = 0; pre < 2; pre++) {
        size_t tbase = bh_base + (size_t)(pre * 64) * 256;
        uint32_t sb = smb + SM_STG + pre * 65536;
        #pragma unroll
        for (int j = 0; j < 4; j++) {
            uint32_t o = j * 4096 + tid * 16;
            cp16(sb + 0     + o, g_pkh + tbase + o);
            cp16(sb + 16384 + o, g_pkl + tbase + o);
            cp16(sb + 32768 + o, g_pvh + tbase + o);
            cp16(sb + 49152 + o, g_pvl + tbase + o);
        }
        CP_COMMIT();
    }

    float o[16][4];
    #pragma unroll
    for (int j = 0; j < 16; j++) { o[j][0] = o[j][1] = o[j][2] = o[j][3] = 0.f; }
    float m_0 = -INFINITY, m_1 = -INFINITY, l_0 = 0.f, l_1 = 0.f;
    const float scale = 0.08838834764831845f;

    int arow = w16 + (tlane & 1) * 8 + ri;
    int acol_half = (tlane >> 1) * 16;
    int brow_in = (tlane >> 1) * 8 + ri;
    int bcol_half = (tlane & 1) * 16;
    int vrow_in = (tlane & 1) * 8 + ri;
    int vcol_half = (tlane >> 1) * 16;

    for (int it = 0; it < 32; it++) {
        int k0 = it * 64;
        uint32_t sb = smb + SM_STG + (it & 1) * 65536;
        const uint32_t KHb = sb, KLb = sb + 16384, VHb = sb + 32768, VLb = sb + 49152;

        CP_WAIT1();           // buffer `it` (and Q on it=0) landed
        __syncthreads();

        // ---- S = Q K^T (3-term split), warp covers 16 rows x 64 cols ----
        float s[8][4];
        #pragma unroll
        for (int j = 0; j < 8; j++) { s[j][0] = s[j][1] = s[j][2] = s[j][3] = 0.f; }

        #pragma unroll
        for (int ks = 0; ks < 8; ks++) {
            uint32_t aH[4], aL[4];
            uint32_t qoff = swz256(arow, ks * 32 + acol_half);
            ldsm4(aH, QHb + qoff);
            ldsm4(aL, QLb + qoff);
            uint32_t bHf[16], bLf[16];
            #pragma unroll
            for (int p = 0; p < 4; p++) {
                uint32_t koff = swz256(p * 16 + brow_in, ks * 32 + bcol_half);
                ldsm4(bHf + p * 4, KHb + koff);
                ldsm4(bLf + p * 4, KLb + koff);
            }
            #pragma unroll
            for (int j = 0; j < 8; j++) {
                uint32_t b0h = bHf[(j >> 1) * 4 + (j & 1) * 2], b1h = bHf[(j >> 1) * 4 + (j & 1) * 2 + 1];
                uint32_t b0l = bLf[(j >> 1) * 4 + (j & 1) * 2], b1l = bLf[(j >> 1) * 4 + (j & 1) * 2 + 1];
                mma16816(s[j], aH, b0h, b1h);
                mma16816(s[j], aL, b0h, b1h);
                mma16816(s[j], aH, b0l, b1l);
            }
        }

        // ---- online softmax (warp-local; rows g and g+8 of this warp) ----
        const float* mr0 = Mb + (size_t)(q0 + w16 + g) * SS + k0;
        const float* mr1 = mr0 + (size_t)8 * SS;
        float mx0 = -INFINITY, mx1 = -INFINITY;
        #pragma unroll
        for (int j = 0; j < 8; j++) {
            float2 mk0 = *(const float2*)(mr0 + j * 8 + tig * 2);
            float2 mk1 = *(const float2*)(mr1 + j * 8 + tig * 2);
            s[j][0] = fmaf(s[j][0], scale, mk0.x);
            s[j][1] = fmaf(s[j][1], scale, mk0.y);
            s[j][2] = fmaf(s[j][2], scale, mk1.x);
            s[j][3] = fmaf(s[j][3], scale, mk1.y);
            mx0 = fmaxf(mx0, fmaxf(s[j][0], s[j][1]));
            mx1 = fmaxf(mx1, fmaxf(s[j][2], s[j][3]));
        }
        mx0 = fmaxf(mx0, __shfl_xor_sync(0xffffffffu, mx0, 1));
        mx0 = fmaxf(mx0, __shfl_xor_sync(0xffffffffu, mx0, 2));
        mx1 = fmaxf(mx1, __shfl_xor_sync(0xffffffffu, mx1, 1));
        mx1 = fmaxf(mx1, __shfl_xor_sync(0xffffffffu, mx1, 2));
        float mn0 = fmaxf(m_0, mx0), mn1 = fmaxf(m_1, mx1);
        float f0 = __expf(m_0 - mn0), f1 = __expf(m_1 - mn1);

        float sum0 = 0.f, sum1 = 0.f;
        #pragma unroll
        for (int j = 0; j < 8; j++) {
            float p00 = __expf(s[j][0] - mn0);
            float p01 = __expf(s[j][1] - mn0);
            float p10 = __expf(s[j][2] - mn1);
            float p11 = __expf(s[j][3] - mn1);
            sum0 += p00 + p01; sum1 += p10 + p11;
            float h00, l00, h01, l01, h10, l10, h11, l11;
            split1(p00, h00, l00); split1(p01, h01, l01);
            split1(p10, h10, l10); split1(p11, h11, l11);
            uint32_t off0 = swz128(w16 + g, j * 16 + tig * 4);
            uint32_t off1 = swz128(w16 + g + 8, j * 16 + tig * 4);
            *(uint32_t*)(smc + SM_PH + off0) = pack_bf16(h00, h01);
            *(uint32_t*)(smc + SM_PL + off0) = pack_bf16(l00, l01);
            *(uint32_t*)(smc + SM_PH + off1) = pack_bf16(h10, h11);
            *(uint32_t*)(smc + SM_PL + off1) = pack_bf16(l10, l11);
        }
        sum0 += __shfl_xor_sync(0xffffffffu, sum0, 1);
        sum0 += __shfl_xor_sync(0xffffffffu, sum0, 2);
        sum1 += __shfl_xor_sync(0xffffffffu, sum1, 1);
        sum1 += __shfl_xor_sync(0xffffffffu, sum1, 2);
        l_0 = l_0 * f0 + sum0; l_1 = l_1 * f1 + sum1;
        m_0 = mn0; m_1 = mn1;

        #pragma unroll
        for (int j = 0; j < 16; j++) {
            o[j][0] *= f0; o[j][1] *= f0;
            o[j][2] *= f1; o[j][3] *= f1;
        }
        __syncwarp();   // P visible to own warp's ldmatrix

        // ---- O += P V (3-term split), 16 rows x 128 cols, kdim 64 ----
        #pragma unroll
        for (int ks = 0; ks < 4; ks++) {
            uint32_t aH[4], aL[4];
            uint32_t poff = swz128(arow, ks * 32 + acol_half);
            ldsm4(aH, PHb + poff);
            ldsm4(aL, PLb + poff);
            #pragma unroll
            for (int p = 0; p < 8; p++) {
                uint32_t vH[4], vL[4];
                uint32_t voff = swz256(ks * 16 + vrow_in, p * 32 + vcol_half);
                ldsm4t(vH, VHb + voff);
                ldsm4t(vL, VLb + voff);
                int j0 = p * 2, j1 = p * 2 + 1;
                mma16816(o[j0], aH, vH[0], vH[1]);
                mma16816(o[j1], aH, vH[2], vH[3]);
                mma16816(o[j0], aL, vH[0], vH[1]);
                mma16816(o[j1], aL, vH[2], vH[3]);
                mma16816(o[j0], aH, vL[0], vL[1]);
                mma16816(o[j1], aH, vL[2], vL[3]);
            }
        }

        __syncthreads();   // all warps done reading stage buffer (it & 1)
        if (it + 2 < 32) {
            size_t tbase = bh_base + (size_t)((it + 2) * 64) * 256;
            uint32_t nb = smb + SM_STG + (it & 1) * 65536;
            #pragma unroll
            for (int j = 0; j < 4; j++) {
                uint32_t oo = j * 4096 + tid * 16;
                cp16(nb + 0     + oo, g_pkh + tbase + oo);
                cp16(nb + 16384 + oo, g_pkl + tbase + oo);
                cp16(nb + 32768 + oo, g_pvh + tbase + oo);
                cp16(nb + 49152 + oo, g_pvl + tbase + oo);
            }
            CP_COMMIT();
        }
    }

    // ---- epilogue: O / l -> gmem (token-major) ----
    int h = bh & 15;
    float inv0 = 1.0f / l_0, inv1 = 1.0f / l_1;
    float* op0 = O + (size_t)(b * SS + q0 + w16 + g) * NF + h * HD;
    float* op1 = op0 + (size_t)8 * NF;
    #pragma unroll
    for (int j = 0; j < 16; j++) {
        *(float2*)(op0 + j * 8 + tig * 2) = make_float2(o[j][0] * inv0, o[j][1] * inv0);
        *(float2*)(op1 + j * 8 + tig * 2) = make_float2(o[j][2] * inv1, o[j][3] * inv1);
    }
}

// ---------------- launch ----------------------------------------------------
extern "C" void kernel_launch(void* const* d_in, const int* in_sizes, int n_in,
                              void* d_out, int out_size) {
    const float* x     = (const float*)d_in[0];
    const float* mask0 = (const float*)d_in[1];
    const float* wq    = (const float*)d_in[2];
    const float* wk    = (const float*)d_in[3];
    const float* wv    = (const float*)d_in[4];
    const float* wo    = (const float*)d_in[5];
    const float* qnw   = (const float*)d_in[6];
    const float* knw   = (const float*)d_in[7];
    float* out = (float*)d_out;

    float *pq, *pk, *pv, *pa;
    cudaGetSymbolAddress((void**)&pq, g_q);
    cudaGetSymbolAddress((void**)&pk, g_k);
    cudaGetSymbolAddress((void**)&pv, g_v);
    cudaGetSymbolAddress((void**)&pa, g_a);

    static bool attr_set = false;
    if (!attr_set) {
        cudaFuncSetAttribute(attn_mma_kernel, cudaFuncAttributeMaxDynamicSharedMemorySize,
                             SM_ATT_TOTAL);
        attr_set = true;
    }

    // 1. RoPE tables
    rope_table_kernel<<<(SS * 64 + 255) / 256, 256>>>();

    // 2. QKV projections (fp32 SIMT)
    gemm_nt_kernel<<<dim3(NT / BM, NF / BN, 3), 256>>>(
        x, wq, wk, wv, pq, pk, pv, NT, NF, DD);

    // 3. per-head RMSNorm + RoPE + split-bf16 plane emit (Q,K,V)
    norm_rope_kernel<<<dim3(HH, NT), 128>>>(qnw, knw);

    // 4. attention (mma.sync bf16 split, cp.async pipelined)
    attn_mma_kernel<<<dim3(SS / 128, BB * HH), 256, SM_ATT_TOTAL>>>(mask0, pa);

    // 5. output projection
    gemm_nt_kernel<<<dim3(NT / BM, DD / BN, 1), 256>>>(
        pa, wo, wo, wo, out, out, out, NT, DD, NF);
}

// round 5
// speedup vs baseline: 4.1666x; 1.3769x over previous
#include <cuda_runtime.h>
#include <cuda_bf16.h>
#include <math.h>
#include <stdint.h>

// Problem dims (fixed by reference)
#define BB 2
#define SS 2048
#define DD 192
#define HH 16
#define HD 128
#define NT (BB*SS)        // 4096 tokens
#define NF (HH*HD)        // 2048 features

// ---------------- scratch (device globals; no allocations allowed) ----------
__device__ float g_q[NT * NF];     // fp32 projection outputs (scratch)
__device__ float g_k[NT * NF];
__device__ float g_v[NT * NF];
__device__ float g_cos[SS * 64];
__device__ float g_sin[SS * 64];

// pre-swizzled split-bf16 planes for attention: [(b*HH+h)][s][256B row, 16B-chunk XOR (s&7)]
#define PLANE_BYTES ((size_t)NT * NF * 2)
__device__ __align__(1024) unsigned char g_pqh[PLANE_BYTES];
__device__ __align__(1024) unsigned char g_pql[PLANE_BYTES];
__device__ __align__(1024) unsigned char g_pkh[PLANE_BYTES];
__device__ __align__(1024) unsigned char g_pkl[PLANE_BYTES];
__device__ __align__(1024) unsigned char g_pvh[PLANE_BYTES];
__device__ __align__(1024) unsigned char g_pvl[PLANE_BYTES];

// linear split-bf16 planes for GEMMs
__device__ __align__(16) __nv_bfloat16 g_xh[NT * DD];       // x
__device__ __align__(16) __nv_bfloat16 g_xl[NT * DD];
__device__ __align__(16) __nv_bfloat16 g_w6h[3 * NF * DD];  // wq|wk|wv stacked
__device__ __align__(16) __nv_bfloat16 g_w6l[3 * NF * DD];
__device__ __align__(16) __nv_bfloat16 g_woh[DD * NF];      // wo
__device__ __align__(16) __nv_bfloat16 g_wol[DD * NF];
__device__ __align__(16) __nv_bfloat16 g_ah[(size_t)NT * NF]; // attention out
__device__ __align__(16) __nv_bfloat16 g_al[(size_t)NT * NF];

// plane byte offset for (bh, s, d)
__device__ __forceinline__ size_t plane_off(int bh, int s, int d) {
    int colb = d * 2;
    int sw = ((((colb >> 4) ^ (s & 7)) << 4) | (colb & 15));
    return ((size_t)bh * SS + s) * 256 + sw;
}

// =======================  warp-MMA helpers (generic PTX, sm_80+) ============
__device__ __forceinline__ uint32_t smem_u32(const void* p) {
    uint32_t a;
    asm("{ .reg .u64 t; cvta.to.shared.u64 t, %1; cvt.u32.u64 %0, t; }"
        : "=r"(a) : "l"(p));
    return a;
}

__device__ __forceinline__ void ldsm4(uint32_t* r, uint32_t addr) {
    asm volatile("ldmatrix.sync.aligned.m8n8.x4.shared.b16 {%0,%1,%2,%3}, [%4];"
        : "=r"(r[0]), "=r"(r[1]), "=r"(r[2]), "=r"(r[3]) : "r"(addr) : "memory");
}
__device__ __forceinline__ void ldsm4t(uint32_t* r, uint32_t addr) {
    asm volatile("ldmatrix.sync.aligned.m8n8.x4.trans.shared.b16 {%0,%1,%2,%3}, [%4];"
        : "=r"(r[0]), "=r"(r[1]), "=r"(r[2]), "=r"(r[3]) : "r"(addr) : "memory");
}

__device__ __forceinline__ void mma16816(float* c, const uint32_t* a, uint32_t b0, uint32_t b1) {
    asm volatile(
        "mma.sync.aligned.m16n8k16.row.col.f32.bf16.bf16.f32 "
        "{%0,%1,%2,%3}, {%4,%5,%6,%7}, {%8,%9}, {%0,%1,%2,%3};"
        : "+f"(c[0]), "+f"(c[1]), "+f"(c[2]), "+f"(c[3])
        : "r"(a[0]), "r"(a[1]), "r"(a[2]), "r"(a[3]), "r"(b0), "r"(b1));
}

__device__ __forceinline__ void cp16(uint32_t smem_dst, const void* gsrc) {
    asm volatile("cp.async.cg.shared.global [%0], [%1], 16;"
        :: "r"(smem_dst), "l"(gsrc) : "memory");
}
#define CP_COMMIT() asm volatile("cp.async.commit_group;" ::: "memory")
#define CP_WAIT1()  asm volatile("cp.async.wait_group 1;" ::: "memory")
#define CP_WAIT0()  asm volatile("cp.async.wait_group 0;" ::: "memory")

__device__ __forceinline__ uint32_t pack_bf16(float a, float b) {
    __nv_bfloat162 t = __floats2bfloat162_rn(a, b);
    return *(uint32_t*)&t;
}
__device__ __forceinline__ void split1(float x, float& hi, float& lo) {
    hi = __bfloat162float(__float2bfloat16(x));
    lo = x - hi;
}

// XOR swizzle at 16B granularity (row stride 256B / 128B)
__device__ __forceinline__ uint32_t swz256(int row, int colb) {
    return (uint32_t)(row * 256 + ((((colb >> 4) ^ (row & 7)) << 4) | (colb & 15)));
}
__device__ __forceinline__ uint32_t swz128(int row, int colb) {
    return (uint32_t)(row * 128 + (((((colb >> 4) ^ (row & 7)) & 7) << 4) | (colb & 15)));
}

// ---------------- RoPE table (fp64-accurate) --------------------------------
__global__ void rope_table_kernel() {
    int i = blockIdx.x * blockDim.x + threadIdx.x;
    if (i >= SS * 64) return;
    int s = i >> 6, f = i & 63;
    double e = ((double)(2 * f) / 128.0) * 13.815510557964274;
    double invf = exp(-e);
    double ph = (double)s * invf;
    g_cos[i] = (float)cos(ph);
    g_sin[i] = (float)sin(ph);
}

// ---------------- split-conversion of x / wq / wk / wv / wo -----------------
__global__ __launch_bounds__(256) void conv_split_kernel(
    const float* __restrict__ x,  const float* __restrict__ wq,
    const float* __restrict__ wk, const float* __restrict__ wv,
    const float* __restrict__ wo)
{
    int z = blockIdx.y;
    int i = blockIdx.x * 256 + threadIdx.x;
    const float* src; __nv_bfloat16 *dh, *dl; int cnt;
    if (z == 0)      { src = x;  dh = g_xh;  dl = g_xl;  cnt = NT * DD; }
    else if (z == 1) { src = wq; dh = g_w6h; dl = g_w6l; cnt = NF * DD; }
    else if (z == 2) { src = wk; dh = g_w6h + NF * DD; dl = g_w6l + NF * DD; cnt = NF * DD; }
    else if (z == 3) { src = wv; dh = g_w6h + 2 * NF * DD; dl = g_w6l + 2 * NF * DD; cnt = NF * DD; }
    else             { src = wo; dh = g_woh; dl = g_wol; cnt = DD * NF; }
    if (i >= cnt) return;
    float v = src[i];
    float hi, lo;
    split1(v, hi, lo);
    dh[i] = __float2bfloat16(hi);
    dl[i] = __float2bfloat16(lo);
}

// ---------- split-bf16 tensor-core GEMM: C[M][N] = A[M][K] * B[N][K]^T ------
// BM=128, BN=64, BK=32. 8 warps (4 x 2), warp tile 32x32. 80B-stride stage rows
// (5 slots mod 8 -> conflict-free ldmatrix). Double-buffered cp.async.
#define GSTG_AH 0
#define GSTG_AL 10240
#define GSTG_BH 20480
#define GSTG_BL 25600
#define GBUF    30720
#define GSM_TOTAL (2 * GBUF)

__global__ __launch_bounds__(256, 2) void gemm_bf16_kernel(
    const __nv_bfloat16* __restrict__ Ah, const __nv_bfloat16* __restrict__ Al,
    const __nv_bfloat16* __restrict__ Bh, const __nv_bfloat16* __restrict__ Bl,
    int lda, int ldb, int K, int mode, float* __restrict__ Cout)
{
    extern __shared__ char gsm[];
    uint32_t smb = smem_u32(gsm);
    int tid = threadIdx.x;
    int w = tid >> 5, lane = tid & 31;
    int wm = w >> 1, wn = w & 1;
    int g = lane >> 2, tig = lane & 3;
    int tlane = lane >> 3, ri = lane & 7;
    int m0 = blockIdx.x * 128, n0 = blockIdx.y * 64;
    int nk = K >> 5;

    float c[2][4][4] = {};

    int a_r = (tlane & 1) * 8 + ri;
    int a_cb = (tlane >> 1) * 16;
    int b_r = (tlane >> 1) * 8 + ri;
    int b_cb = (tlane & 1) * 16;

    auto load_buf = [&](int kt, uint32_t sb) {
        int k0e = kt << 5;                  // k offset in elements
        for (int i = tid; i < 512; i += 256) {
            int r = i >> 2, cB = (i & 3) * 16;
            uint32_t d = sb + r * 80 + cB;
            const char* sh = (const char*)(Ah + (size_t)(m0 + r) * lda + k0e) + cB;
            const char* sl = (const char*)(Al + (size_t)(m0 + r) * lda + k0e) + cB;
            cp16(d + GSTG_AH, sh);
            cp16(d + GSTG_AL, sl);
        }
        for (int i = tid; i < 256; i += 256) {
            int r = i >> 2, cB = (i & 3) * 16;
            uint32_t d = sb + r * 80 + cB;
            const char* sh = (const char*)(Bh + (size_t)(n0 + r) * ldb + k0e) + cB;
            const char* sl = (const char*)(Bl + (size_t)(n0 + r) * ldb + k0e) + cB;
            cp16(d + GSTG_BH, sh);
            cp16(d + GSTG_BL, sl);
        }
    };

    load_buf(0, smb);
    CP_COMMIT();

    for (int kt = 0; kt < nk; kt++) {
        uint32_t sb = smb + (kt & 1) * GBUF;
        if (kt + 1 < nk) {
            __syncthreads();                 // prev compute done on target buffer
            load_buf(kt + 1, smb + ((kt + 1) & 1) * GBUF);
            CP_COMMIT();
            CP_WAIT1();
        } else {
            CP_WAIT0();
        }
        __syncthreads();

        #pragma unroll
        for (int ks = 0; ks < 2; ks++) {
            uint32_t aH[2][4], aL[2][4];
            #pragma unroll
            for (int mf = 0; mf < 2; mf++) {
                uint32_t ad = sb + (uint32_t)((wm * 32 + mf * 16 + a_r) * 80 + ks * 32 + a_cb);
                ldsm4(aH[mf], ad + GSTG_AH);
                ldsm4(aL[mf], ad + GSTG_AL);
            }
            uint32_t bH[2][4], bL[2][4];
            #pragma unroll
            for (int nt = 0; nt < 2; nt++) {
                uint32_t bd = sb + (uint32_t)((wn * 32 + nt * 16 + b_r) * 80 + ks * 32 + b_cb);
                ldsm4(bH[nt], bd + GSTG_BH);
                ldsm4(bL[nt], bd + GSTG_BL);
            }
            #pragma unroll
            for (int mf = 0; mf < 2; mf++) {
                #pragma unroll
                for (int nt = 0; nt < 2; nt++) {
                    float* c0 = c[mf][nt * 2];
                    float* c1 = c[mf][nt * 2 + 1];
                    mma16816(c0, aH[mf], bH[nt][0], bH[nt][1]);
                    mma16816(c0, aL[mf], bH[nt][0], bH[nt][1]);
                    mma16816(c0, aH[mf], bL[nt][0], bL[nt][1]);
                    mma16816(c1, aH[mf], bH[nt][2], bH[nt][3]);
                    mma16816(c1, aL[mf], bH[nt][2], bH[nt][3]);
                    mma16816(c1, aH[mf], bL[nt][2], bL[nt][3]);
                }
            }
        }
    }

    // epilogue
    #pragma unroll
    for (int mf = 0; mf < 2; mf++) {
        int row0 = m0 + wm * 32 + mf * 16 + g;
        #pragma unroll
        for (int nn = 0; nn < 4; nn++) {
            int colg = n0 + wn * 32 + nn * 8 + tig * 2;
            float2 v0 = make_float2(c[mf][nn][0], c[mf][nn][1]);
            float2 v1 = make_float2(c[mf][nn][2], c[mf][nn][3]);
            if (mode == 0) {
                int which = colg >> 11, cc = colg & 2047;
                float* dstp = (which == 0) ? g_q : (which == 1) ? g_k : g_v;
                *(float2*)(dstp + (size_t)row0 * NF + cc) = v0;
                *(float2*)(dstp + (size_t)(row0 + 8) * NF + cc) = v1;
            } else {
                *(float2*)(Cout + (size_t)row0 * DD + colg) = v0;
                *(float2*)(Cout + (size_t)(row0 + 8) * DD + colg) = v1;
            }
        }
    }
}

// ------ per-head RMSNorm + RoPE + split-bf16 plane emit (Q, K, V) -----------
__global__ __launch_bounds__(128) void norm_rope_kernel(
    const float* __restrict__ qw, const float* __restrict__ kw)
{
    int h = blockIdx.x;
    int t = blockIdx.y;
    int d = threadIdx.x;
    int s = t & (SS - 1);
    int b = t >> 11;
    int bh = b * HH + h;

    const float* qp = g_q + (size_t)t * NF + h * HD;
    const float* kp = g_k + (size_t)t * NF + h * HD;
    const float* vp = g_v + (size_t)t * NF + h * HD;
    float q = qp[d];
    float k = kp[d];
    float v = vp[d];

    float sq = q * q, sk = k * k;
    #pragma unroll
    for (int m = 16; m; m >>= 1) {
        sq += __shfl_xor_sync(0xffffffffu, sq, m);
        sk += __shfl_xor_sync(0xffffffffu, sk, m);
    }
    __shared__ float rq[4], rk[4];
    __shared__ float shq[HD], shk[HD];
    int wid = d >> 5, lane = d & 31;
    if (lane == 0) { rq[wid] = sq; rk[wid] = sk; }
    __syncthreads();
    float ssq = rq[0] + rq[1] + rq[2] + rq[3];
    float ssk = rk[0] + rk[1] + rk[2] + rk[3];
    float rinvq = rsqrtf(ssq * (1.0f / HD) + 1e-6f);
    float rinvk = rsqrtf(ssk * (1.0f / HD) + 1e-6f);
    float qn = q * rinvq * qw[d];
    float kn = k * rinvk * kw[d];
    shq[d] = qn; shk[d] = kn;
    __syncthreads();

    int f = d & 63;
    float c = g_cos[s * 64 + f];
    float sn = g_sin[s * 64 + f];
    float qo, ko;
    if (d < 64) {
        qo = qn * c - shq[d + 64] * sn;
        ko = kn * c - shk[d + 64] * sn;
    } else {
        qo = qn * c + shq[d - 64] * sn;
        ko = kn * c + shk[d - 64] * sn;
    }

    size_t po = plane_off(bh, s, d);
    float hi, lo;
    split1(qo, hi, lo);
    *(__nv_bfloat16*)(g_pqh + po) = __float2bfloat16(hi);
    *(__nv_bfloat16*)(g_pql + po) = __float2bfloat16(lo);
    split1(ko, hi, lo);
    *(__nv_bfloat16*)(g_pkh + po) = __float2bfloat16(hi);
    *(__nv_bfloat16*)(g_pkl + po) = __float2bfloat16(lo);
    split1(v, hi, lo);
    *(__nv_bfloat16*)(g_pvh + po) = __float2bfloat16(hi);
    *(__nv_bfloat16*)(g_pvl + po) = __float2bfloat16(lo);
}

// ========== mma.sync flash attention, pipelined cp.async staging ============
#define SM_QH 0
#define SM_QL 32768
#define SM_PH 65536
#define SM_PL 81920
#define SM_STG 98304          // two 64KB stage buffers: {KH,KL,VH,VL} x 16KB
#define SM_ATT_TOTAL (SM_STG + 2 * 65536)   // 229376

__global__ __launch_bounds__(256, 1) void attn_mma_kernel(const float* __restrict__ mask)
{
    extern __shared__ char smc[];
    uint32_t smb = smem_u32(smc);
    const uint32_t QHb = smb + SM_QH, QLb = smb + SM_QL;
    const uint32_t PHb = smb + SM_PH, PLb = smb + SM_PL;

    int tid = threadIdx.x;
    int w = tid >> 5, lane = tid & 31;
    int w16 = w * 16;
    int g = lane >> 2, tig = lane & 3;
    int tlane = lane >> 3, ri = lane & 7;

    int q0 = blockIdx.x * 128;
    int bh = blockIdx.y;
    int b = bh >> 4;

    const float* Mb = mask + (size_t)b * SS * SS;
    size_t bh_base = (size_t)bh * SS * 256;

    {
        size_t qbase = bh_base + (size_t)q0 * 256;
        #pragma unroll
        for (int j = 0; j < 8; j++) {
            uint32_t o = j * 4096 + tid * 16;
            cp16(QHb + o, g_pqh + qbase + o);
            cp16(QLb + o, g_pql + qbase + o);
        }
        CP_COMMIT();
    }
    #pragma unroll
    for (int pre = 0; pre < 2; pre++) {
        size_t tbase = bh_base + (size_t)(pre * 64) * 256;
        uint32_t sb = smb + SM_STG + pre * 65536;
        #pragma unroll
        for (int j = 0; j < 4; j++) {
            uint32_t o = j * 4096 + tid * 16;
            cp16(sb + 0     + o, g_pkh + tbase + o);
            cp16(sb + 16384 + o, g_pkl + tbase + o);
            cp16(sb + 32768 + o, g_pvh + tbase + o);
            cp16(sb + 49152 + o, g_pvl + tbase + o);
        }
        CP_COMMIT();
    }

    float o[16][4];
    #pragma unroll
    for (int j = 0; j < 16; j++) { o[j][0] = o[j][1] = o[j][2] = o[j][3] = 0.f; }
    float m_0 = -INFINITY, m_1 = -INFINITY, l_0 = 0.f, l_1 = 0.f;
    const float scale = 0.08838834764831845f;

    int arow = w16 + (tlane & 1) * 8 + ri;
    int acol_half = (tlane >> 1) * 16;
    int brow_in = (tlane >> 1) * 8 + ri;
    int bcol_half = (tlane & 1) * 16;
    int vrow_in = (tlane & 1) * 8 + ri;
    int vcol_half = (tlane >> 1) * 16;

    for (int it = 0; it < 32; it++) {
        int k0 = it * 64;
        uint32_t sb = smb + SM_STG + (it & 1) * 65536;
        const uint32_t KHb = sb, KLb = sb + 16384, VHb = sb + 32768, VLb = sb + 49152;

        CP_WAIT1();
        __syncthreads();

        float s[8][4];
        #pragma unroll
        for (int j = 0; j < 8; j++) { s[j][0] = s[j][1] = s[j][2] = s[j][3] = 0.f; }

        #pragma unroll
        for (int ks = 0; ks < 8; ks++) {
            uint32_t aH[4], aL[4];
            uint32_t qoff = swz256(arow, ks * 32 + acol_half);
            ldsm4(aH, QHb + qoff);
            ldsm4(aL, QLb + qoff);
            uint32_t bHf[16], bLf[16];
            #pragma unroll
            for (int p = 0; p < 4; p++) {
                uint32_t koff = swz256(p * 16 + brow_in, ks * 32 + bcol_half);
                ldsm4(bHf + p * 4, KHb + koff);
                ldsm4(bLf + p * 4, KLb + koff);
            }
            #pragma unroll
            for (int j = 0; j < 8; j++) {
                uint32_t b0h = bHf[(j >> 1) * 4 + (j & 1) * 2], b1h = bHf[(j >> 1) * 4 + (j & 1) * 2 + 1];
                uint32_t b0l = bLf[(j >> 1) * 4 + (j & 1) * 2], b1l = bLf[(j >> 1) * 4 + (j & 1) * 2 + 1];
                mma16816(s[j], aH, b0h, b1h);
                mma16816(s[j], aL, b0h, b1h);
                mma16816(s[j], aH, b0l, b1l);
            }
        }

        const float* mr0 = Mb + (size_t)(q0 + w16 + g) * SS + k0;
        const float* mr1 = mr0 + (size_t)8 * SS;
        float mx0 = -INFINITY, mx1 = -INFINITY;
        #pragma unroll
        for (int j = 0; j < 8; j++) {
            float2 mk0 = *(const float2*)(mr0 + j * 8 + tig * 2);
            float2 mk1 = *(const float2*)(mr1 + j * 8 + tig * 2);
            s[j][0] = fmaf(s[j][0], scale, mk0.x);
            s[j][1] = fmaf(s[j][1], scale, mk0.y);
            s[j][2] = fmaf(s[j][2], scale, mk1.x);
            s[j][3] = fmaf(s[j][3], scale, mk1.y);
            mx0 = fmaxf(mx0, fmaxf(s[j][0], s[j][1]));
            mx1 = fmaxf(mx1, fmaxf(s[j][2], s[j][3]));
        }
        mx0 = fmaxf(mx0, __shfl_xor_sync(0xffffffffu, mx0, 1));
        mx0 = fmaxf(mx0, __shfl_xor_sync(0xffffffffu, mx0, 2));
        mx1 = fmaxf(mx1, __shfl_xor_sync(0xffffffffu, mx1, 1));
        mx1 = fmaxf(mx1, __shfl_xor_sync(0xffffffffu, mx1, 2));
        float mn0 = fmaxf(m_0, mx0), mn1 = fmaxf(m_1, mx1);
        float f0 = __expf(m_0 - mn0), f1 = __expf(m_1 - mn1);

        float sum0 = 0.f, sum1 = 0.f;
        #pragma unroll
        for (int j = 0; j < 8; j++) {
            float p00 = __expf(s[j][0] - mn0);
            float p01 = __expf(s[j][1] - mn0);
            float p10 = __expf(s[j][2] - mn1);
            float p11 = __expf(s[j][3] - mn1);
            sum0 += p00 + p01; sum1 += p10 + p11;
            float h00, l00, h01, l01, h10, l10, h11, l11;
            split1(p00, h00, l00); split1(p01, h01, l01);
            split1(p10, h10, l10); split1(p11, h11, l11);
            uint32_t off0 = swz128(w16 + g, j * 16 + tig * 4);
            uint32_t off1 = swz128(w16 + g + 8, j * 16 + tig * 4);
            *(uint32_t*)(smc + SM_PH + off0) = pack_bf16(h00, h01);
            *(uint32_t*)(smc + SM_PL + off0) = pack_bf16(l00, l01);
            *(uint32_t*)(smc + SM_PH + off1) = pack_bf16(h10, h11);
            *(uint32_t*)(smc + SM_PL + off1) = pack_bf16(l10, l11);
        }
        sum0 += __shfl_xor_sync(0xffffffffu, sum0, 1);
        sum0 += __shfl_xor_sync(0xffffffffu, sum0, 2);
        sum1 += __shfl_xor_sync(0xffffffffu, sum1, 1);
        sum1 += __shfl_xor_sync(0xffffffffu, sum1, 2);
        l_0 = l_0 * f0 + sum0; l_1 = l_1 * f1 + sum1;
        m_0 = mn0; m_1 = mn1;

        #pragma unroll
        for (int j = 0; j < 16; j++) {
            o[j][0] *= f0; o[j][1] *= f0;
            o[j][2] *= f1; o[j][3] *= f1;
        }
        __syncwarp();

        #pragma unroll
        for (int ks = 0; ks < 4; ks++) {
            uint32_t aH[4], aL[4];
            uint32_t poff = swz128(arow, ks * 32 + acol_half);
            ldsm4(aH, PHb + poff);
            ldsm4(aL, PLb + poff);
            #pragma unroll
            for (int p = 0; p < 8; p++) {
                uint32_t vH[4], vL[4];
                uint32_t voff = swz256(ks * 16 + vrow_in, p * 32 + vcol_half);
                ldsm4t(vH, VHb + voff);
                ldsm4t(vL, VLb + voff);
                int j0 = p * 2, j1 = p * 2 + 1;
                mma16816(o[j0], aH, vH[0], vH[1]);
                mma16816(o[j1], aH, vH[2], vH[3]);
                mma16816(o[j0], aL, vH[0], vH[1]);
                mma16816(o[j1], aL, vH[2], vH[3]);
                mma16816(o[j0], aH, vL[0], vL[1]);
                mma16816(o[j1], aH, vL[2], vL[3]);
            }
        }

        __syncthreads();
        if (it + 2 < 32) {
            size_t tbase = bh_base + (size_t)((it + 2) * 64) * 256;
            uint32_t nb = smb + SM_STG + (it & 1) * 65536;
            #pragma unroll
            for (int j = 0; j < 4; j++) {
                uint32_t oo = j * 4096 + tid * 16;
                cp16(nb + 0     + oo, g_pkh + tbase + oo);
                cp16(nb + 16384 + oo, g_pkl + tbase + oo);
                cp16(nb + 32768 + oo, g_pvh + tbase + oo);
                cp16(nb + 49152 + oo, g_pvl + tbase + oo);
            }
            CP_COMMIT();
        }
    }

    // ---- epilogue: O / l -> split-bf16 planes for the output projection ----
    int h = bh & 15;
    float inv0 = 1.0f / l_0, inv1 = 1.0f / l_1;
    size_t t0 = (size_t)(b * SS + q0 + w16 + g);
    size_t t1 = t0 + 8;
    #pragma unroll
    for (int j = 0; j < 16; j++) {
        int colg = h * HD + j * 8 + tig * 2;
        float v0 = o[j][0] * inv0, v1 = o[j][1] * inv0;
        float u0 = o[j][2] * inv1, u1 = o[j][3] * inv1;
        float h0, l0s, h1, l1s;
        split1(v0, h0, l0s); split1(v1, h1, l1s);
        *(uint32_t*)&g_ah[t0 * NF + colg] = pack_bf16(h0, h1);
        *(uint32_t*)&g_al[t0 * NF + colg] = pack_bf16(l0s, l1s);
        split1(u0, h0, l0s); split1(u1, h1, l1s);
        *(uint32_t*)&g_ah[t1 * NF + colg] = pack_bf16(h0, h1);
        *(uint32_t*)&g_al[t1 * NF + colg] = pack_bf16(l0s, l1s);
    }
}

// ---------------- launch ----------------------------------------------------
extern "C" void kernel_launch(void* const* d_in, const int* in_sizes, int n_in,
                              void* d_out, int out_size) {
    const float* x     = (const float*)d_in[0];
    const float* mask0 = (const float*)d_in[1];
    const float* wq    = (const float*)d_in[2];
    const float* wk    = (const float*)d_in[3];
    const float* wv    = (const float*)d_in[4];
    const float* wo    = (const float*)d_in[5];
    const float* qnw   = (const float*)d_in[6];
    const float* knw   = (const float*)d_in[7];
    float* out = (float*)d_out;

    __nv_bfloat16 *pxh, *pxl, *pw6h, *pw6l, *pwoh, *pwol, *pah, *pal;
    cudaGetSymbolAddress((void**)&pxh, g_xh);
    cudaGetSymbolAddress((void**)&pxl, g_xl);
    cudaGetSymbolAddress((void**)&pw6h, g_w6h);
    cudaGetSymbolAddress((void**)&pw6l, g_w6l);
    cudaGetSymbolAddress((void**)&pwoh, g_woh);
    cudaGetSymbolAddress((void**)&pwol, g_wol);
    cudaGetSymbolAddress((void**)&pah, g_ah);
    cudaGetSymbolAddress((void**)&pal, g_al);

    static bool attr_set = false;
    if (!attr_set) {
        cudaFuncSetAttribute(attn_mma_kernel, cudaFuncAttributeMaxDynamicSharedMemorySize,
                             SM_ATT_TOTAL);
        cudaFuncSetAttribute(gemm_bf16_kernel, cudaFuncAttributeMaxDynamicSharedMemorySize,
                             GSM_TOTAL);
        attr_set = true;
    }

    // 1. RoPE tables
    rope_table_kernel<<<(SS * 64 + 255) / 256, 256>>>();

    // 2. split-bf16 conversion of x and all weights
    conv_split_kernel<<<dim3((NT * DD + 255) / 256, 5), 256>>>(x, wq, wk, wv, wo);

    // 3. QKV projections (tensor-core split-bf16): [4096,192] x [6144,192]^T
    gemm_bf16_kernel<<<dim3(NT / 128, (3 * NF) / 64), 256, GSM_TOTAL>>>(
        pxh, pxl, pw6h, pw6l, DD, DD, DD, 0, out);

    // 4. per-head RMSNorm + RoPE + attention-plane emit
    norm_rope_kernel<<<dim3(HH, NT), 128>>>(qnw, knw);

    // 5. attention (mma.sync bf16 split, cp.async pipelined)
    attn_mma_kernel<<<dim3(SS / 128, BB * HH), 256, SM_ATT_TOTAL>>>(mask0);

    // 6. output projection: [4096,2048] x [192,2048]^T -> d_out
    gemm_bf16_kernel<<<dim3(NT / 128, DD / 64), 256, GSM_TOTAL>>>(
        pah, pal, pwoh, pwol, NF, NF, NF, 1, out);
}

// round 6
// speedup vs baseline: 4.3456x; 1.0430x over previous
#include <cuda_runtime.h>
#include <cuda_bf16.h>
#include <math.h>
#include <stdint.h>

// Problem dims (fixed by reference)
#define BB 2
#define SS 2048
#define DD 192
#define HH 16
#define HD 128
#define NT (BB*SS)        // 4096 tokens
#define NF (HH*HD)        // 2048 features

// ---------------- scratch (device globals; no allocations allowed) ----------
__device__ float g_q[NT * NF];     // fp32 projection outputs (scratch)
__device__ float g_k[NT * NF];
__device__ float g_v[NT * NF];
__device__ float g_cos[SS * 64];
__device__ float g_sin[SS * 64];

// pre-swizzled split-bf16 planes for attention: [(b*HH+h)][s][256B row, 16B-chunk XOR (s&7)]
#define PLANE_BYTES ((size_t)NT * NF * 2)
__device__ __align__(1024) unsigned char g_pqh[PLANE_BYTES];
__device__ __align__(1024) unsigned char g_pql[PLANE_BYTES];
__device__ __align__(1024) unsigned char g_pkh[PLANE_BYTES];
__device__ __align__(1024) unsigned char g_pkl[PLANE_BYTES];
__device__ __align__(1024) unsigned char g_pvh[PLANE_BYTES];
__device__ __align__(1024) unsigned char g_pvl[PLANE_BYTES];

// linear split-bf16 planes for GEMMs
__device__ __align__(16) __nv_bfloat16 g_xh[NT * DD];       // x
__device__ __align__(16) __nv_bfloat16 g_xl[NT * DD];
__device__ __align__(16) __nv_bfloat16 g_w6h[3 * NF * DD];  // wq|wk|wv stacked
__device__ __align__(16) __nv_bfloat16 g_w6l[3 * NF * DD];
__device__ __align__(16) __nv_bfloat16 g_woh[DD * NF];      // wo
__device__ __align__(16) __nv_bfloat16 g_wol[DD * NF];
__device__ __align__(16) __nv_bfloat16 g_ah[(size_t)NT * NF]; // attention out
__device__ __align__(16) __nv_bfloat16 g_al[(size_t)NT * NF];

// plane byte offset for (bh, s, d)
__device__ __forceinline__ size_t plane_off(int bh, int s, int d) {
    int colb = d * 2;
    int sw = ((((colb >> 4) ^ (s & 7)) << 4) | (colb & 15));
    return ((size_t)bh * SS + s) * 256 + sw;
}

// =======================  warp-MMA helpers (generic PTX, sm_80+) ============
__device__ __forceinline__ uint32_t smem_u32(const void* p) {
    uint32_t a;
    asm("{ .reg .u64 t; cvta.to.shared.u64 t, %1; cvt.u32.u64 %0, t; }"
        : "=r"(a) : "l"(p));
    return a;
}

__device__ __forceinline__ void ldsm4(uint32_t* r, uint32_t addr) {
    asm volatile("ldmatrix.sync.aligned.m8n8.x4.shared.b16 {%0,%1,%2,%3}, [%4];"
        : "=r"(r[0]), "=r"(r[1]), "=r"(r[2]), "=r"(r[3]) : "r"(addr) : "memory");
}
__device__ __forceinline__ void ldsm4t(uint32_t* r, uint32_t addr) {
    asm volatile("ldmatrix.sync.aligned.m8n8.x4.trans.shared.b16 {%0,%1,%2,%3}, [%4];"
        : "=r"(r[0]), "=r"(r[1]), "=r"(r[2]), "=r"(r[3]) : "r"(addr) : "memory");
}

__device__ __forceinline__ void mma16816(float* c, const uint32_t* a, uint32_t b0, uint32_t b1) {
    asm volatile(
        "mma.sync.aligned.m16n8k16.row.col.f32.bf16.bf16.f32 "
        "{%0,%1,%2,%3}, {%4,%5,%6,%7}, {%8,%9}, {%0,%1,%2,%3};"
        : "+f"(c[0]), "+f"(c[1]), "+f"(c[2]), "+f"(c[3])
        : "r"(a[0]), "r"(a[1]), "r"(a[2]), "r"(a[3]), "r"(b0), "r"(b1));
}

__device__ __forceinline__ void cp16(uint32_t smem_dst, const void* gsrc) {
    asm volatile("cp.async.cg.shared.global [%0], [%1], 16;"
        :: "r"(smem_dst), "l"(gsrc) : "memory");
}
#define CP_COMMIT() asm volatile("cp.async.commit_group;" ::: "memory")
#define CP_WAIT1()  asm volatile("cp.async.wait_group 1;" ::: "memory")
#define CP_WAIT0()  asm volatile("cp.async.wait_group 0;" ::: "memory")

__device__ __forceinline__ uint32_t pack_bf16(float a, float b) {
    __nv_bfloat162 t = __floats2bfloat162_rn(a, b);
    return *(uint32_t*)&t;
}
__device__ __forceinline__ void split1(float x, float& hi, float& lo) {
    hi = __bfloat162float(__float2bfloat16(x));
    lo = x - hi;
}

// XOR swizzle at 16B granularity (row stride 256B)
__device__ __forceinline__ uint32_t swz256(int row, int colb) {
    return (uint32_t)(row * 256 + ((((colb >> 4) ^ (row & 7)) << 4) | (colb & 15)));
}

// ---------------- RoPE table (fp64-accurate) --------------------------------
__global__ void rope_table_kernel() {
    int i = blockIdx.x * blockDim.x + threadIdx.x;
    if (i >= SS * 64) return;
    int s = i >> 6, f = i & 63;
    double e = ((double)(2 * f) / 128.0) * 13.815510557964274;
    double invf = exp(-e);
    double ph = (double)s * invf;
    g_cos[i] = (float)cos(ph);
    g_sin[i] = (float)sin(ph);
}

// ---------------- split-conversion of x / wq / wk / wv / wo -----------------
__global__ __launch_bounds__(256) void conv_split_kernel(
    const float* __restrict__ x,  const float* __restrict__ wq,
    const float* __restrict__ wk, const float* __restrict__ wv,
    const float* __restrict__ wo)
{
    int z = blockIdx.y;
    int i = blockIdx.x * 256 + threadIdx.x;
    const float* src; __nv_bfloat16 *dh, *dl; int cnt;
    if (z == 0)      { src = x;  dh = g_xh;  dl = g_xl;  cnt = NT * DD; }
    else if (z == 1) { src = wq; dh = g_w6h; dl = g_w6l; cnt = NF * DD; }
    else if (z == 2) { src = wk; dh = g_w6h + NF * DD; dl = g_w6l + NF * DD; cnt = NF * DD; }
    else if (z == 3) { src = wv; dh = g_w6h + 2 * NF * DD; dl = g_w6l + 2 * NF * DD; cnt = NF * DD; }
    else             { src = wo; dh = g_woh; dl = g_wol; cnt = DD * NF; }
    if (i >= cnt) return;
    float v = src[i];
    float hi, lo;
    split1(v, hi, lo);
    dh[i] = __float2bfloat16(hi);
    dl[i] = __float2bfloat16(lo);
}

// ---------- split-bf16 tensor-core GEMM: C[M][N] = A[M][K] * B[N][K]^T ------
#define GSTG_AH 0
#define GSTG_AL 10240
#define GSTG_BH 20480
#define GSTG_BL 25600
#define GBUF    30720
#define GSM_TOTAL (2 * GBUF)

__global__ __launch_bounds__(256, 2) void gemm_bf16_kernel(
    const __nv_bfloat16* __restrict__ Ah, const __nv_bfloat16* __restrict__ Al,
    const __nv_bfloat16* __restrict__ Bh, const __nv_bfloat16* __restrict__ Bl,
    int lda, int ldb, int K, int mode, float* __restrict__ Cout)
{
    extern __shared__ char gsm[];
    uint32_t smb = smem_u32(gsm);
    int tid = threadIdx.x;
    int w = tid >> 5, lane = tid & 31;
    int wm = w >> 1, wn = w & 1;
    int g = lane >> 2, tig = lane & 3;
    int tlane = lane >> 3, ri = lane & 7;
    int m0 = blockIdx.x * 128, n0 = blockIdx.y * 64;
    int nk = K >> 5;

    float c[2][4][4] = {};

    int a_r = (tlane & 1) * 8 + ri;
    int a_cb = (tlane >> 1) * 16;
    int b_r = (tlane >> 1) * 8 + ri;
    int b_cb = (tlane & 1) * 16;

    auto load_buf = [&](int kt, uint32_t sb) {
        int k0e = kt << 5;
        for (int i = tid; i < 512; i += 256) {
            int r = i >> 2, cB = (i & 3) * 16;
            uint32_t d = sb + r * 80 + cB;
            const char* sh = (const char*)(Ah + (size_t)(m0 + r) * lda + k0e) + cB;
            const char* sl = (const char*)(Al + (size_t)(m0 + r) * lda + k0e) + cB;
            cp16(d + GSTG_AH, sh);
            cp16(d + GSTG_AL, sl);
        }
        for (int i = tid; i < 256; i += 256) {
            int r = i >> 2, cB = (i & 3) * 16;
            uint32_t d = sb + r * 80 + cB;
            const char* sh = (const char*)(Bh + (size_t)(n0 + r) * ldb + k0e) + cB;
            const char* sl = (const char*)(Bl + (size_t)(n0 + r) * ldb + k0e) + cB;
            cp16(d + GSTG_BH, sh);
            cp16(d + GSTG_BL, sl);
        }
    };

    load_buf(0, smb);
    CP_COMMIT();

    for (int kt = 0; kt < nk; kt++) {
        uint32_t sb = smb + (kt & 1) * GBUF;
        if (kt + 1 < nk) {
            __syncthreads();
            load_buf(kt + 1, smb + ((kt + 1) & 1) * GBUF);
            CP_COMMIT();
            CP_WAIT1();
        } else {
            CP_WAIT0();
        }
        __syncthreads();

        #pragma unroll
        for (int ks = 0; ks < 2; ks++) {
            uint32_t aH[2][4], aL[2][4];
            #pragma unroll
            for (int mf = 0; mf < 2; mf++) {
                uint32_t ad = sb + (uint32_t)((wm * 32 + mf * 16 + a_r) * 80 + ks * 32 + a_cb);
                ldsm4(aH[mf], ad + GSTG_AH);
                ldsm4(aL[mf], ad + GSTG_AL);
            }
            uint32_t bH[2][4], bL[2][4];
            #pragma unroll
            for (int nt = 0; nt < 2; nt++) {
                uint32_t bd = sb + (uint32_t)((wn * 32 + nt * 16 + b_r) * 80 + ks * 32 + b_cb);
                ldsm4(bH[nt], bd + GSTG_BH);
                ldsm4(bL[nt], bd + GSTG_BL);
            }
            #pragma unroll
            for (int mf = 0; mf < 2; mf++) {
                #pragma unroll
                for (int nt = 0; nt < 2; nt++) {
                    float* c0 = c[mf][nt * 2];
                    float* c1 = c[mf][nt * 2 + 1];
                    mma16816(c0, aH[mf], bH[nt][0], bH[nt][1]);
                    mma16816(c0, aL[mf], bH[nt][0], bH[nt][1]);
                    mma16816(c0, aH[mf], bL[nt][0], bL[nt][1]);
                    mma16816(c1, aH[mf], bH[nt][2], bH[nt][3]);
                    mma16816(c1, aL[mf], bH[nt][2], bH[nt][3]);
                    mma16816(c1, aH[mf], bL[nt][2], bL[nt][3]);
                }
            }
        }
    }

    #pragma unroll
    for (int mf = 0; mf < 2; mf++) {
        int row0 = m0 + wm * 32 + mf * 16 + g;
        #pragma unroll
        for (int nn = 0; nn < 4; nn++) {
            int colg = n0 + wn * 32 + nn * 8 + tig * 2;
            float2 v0 = make_float2(c[mf][nn][0], c[mf][nn][1]);
            float2 v1 = make_float2(c[mf][nn][2], c[mf][nn][3]);
            if (mode == 0) {
                int which = colg >> 11, cc = colg & 2047;
                float* dstp = (which == 0) ? g_q : (which == 1) ? g_k : g_v;
                *(float2*)(dstp + (size_t)row0 * NF + cc) = v0;
                *(float2*)(dstp + (size_t)(row0 + 8) * NF + cc) = v1;
            } else {
                *(float2*)(Cout + (size_t)row0 * DD + colg) = v0;
                *(float2*)(Cout + (size_t)(row0 + 8) * DD + colg) = v1;
            }
        }
    }
}

// ------ per-head RMSNorm + RoPE + split-bf16 plane emit (Q, K, V) -----------
__global__ __launch_bounds__(128) void norm_rope_kernel(
    const float* __restrict__ qw, const float* __restrict__ kw)
{
    int h = blockIdx.x;
    int t = blockIdx.y;
    int d = threadIdx.x;
    int s = t & (SS - 1);
    int b = t >> 11;
    int bh = b * HH + h;

    const float* qp = g_q + (size_t)t * NF + h * HD;
    const float* kp = g_k + (size_t)t * NF + h * HD;
    const float* vp = g_v + (size_t)t * NF + h * HD;
    float q = qp[d];
    float k = kp[d];
    float v = vp[d];

    float sq = q * q, sk = k * k;
    #pragma unroll
    for (int m = 16; m; m >>= 1) {
        sq += __shfl_xor_sync(0xffffffffu, sq, m);
        sk += __shfl_xor_sync(0xffffffffu, sk, m);
    }
    __shared__ float rq[4], rk[4];
    __shared__ float shq[HD], shk[HD];
    int wid = d >> 5, lane = d & 31;
    if (lane == 0) { rq[wid] = sq; rk[wid] = sk; }
    __syncthreads();
    float ssq = rq[0] + rq[1] + rq[2] + rq[3];
    float ssk = rk[0] + rk[1] + rk[2] + rk[3];
    float rinvq = rsqrtf(ssq * (1.0f / HD) + 1e-6f);
    float rinvk = rsqrtf(ssk * (1.0f / HD) + 1e-6f);
    float qn = q * rinvq * qw[d];
    float kn = k * rinvk * kw[d];
    shq[d] = qn; shk[d] = kn;
    __syncthreads();

    int f = d & 63;
    float c = g_cos[s * 64 + f];
    float sn = g_sin[s * 64 + f];
    float qo, ko;
    if (d < 64) {
        qo = qn * c - shq[d + 64] * sn;
        ko = kn * c - shk[d + 64] * sn;
    } else {
        qo = qn * c + shq[d - 64] * sn;
        ko = kn * c + shk[d - 64] * sn;
    }

    size_t po = plane_off(bh, s, d);
    float hi, lo;
    split1(qo, hi, lo);
    *(__nv_bfloat16*)(g_pqh + po) = __float2bfloat16(hi);
    *(__nv_bfloat16*)(g_pql + po) = __float2bfloat16(lo);
    split1(ko, hi, lo);
    *(__nv_bfloat16*)(g_pkh + po) = __float2bfloat16(hi);
    *(__nv_bfloat16*)(g_pkl + po) = __float2bfloat16(lo);
    split1(v, hi, lo);
    *(__nv_bfloat16*)(g_pvh + po) = __float2bfloat16(hi);
    *(__nv_bfloat16*)(g_pvl + po) = __float2bfloat16(lo);
}

// ===== mma.sync flash attention, Br=64 x Bc=32, 128 thr, 2 CTAs/SM ==========
// smem byte offsets
#define A_QH 0                      // 64 rows x 256B
#define A_QL 16384
#define A_PH 32768                  // 64 rows x 80B  (5120B)
#define A_PL 37888
#define A_STG 43008                 // two 32KB buffers: {KH,KL,VH,VL} x 8KB
#define A_BUF 32768
#define SM_ATT_TOTAL (A_STG + 2 * A_BUF)    // 108544

__global__ __launch_bounds__(128, 2) void attn_mma_kernel(const float* __restrict__ mask)
{
    extern __shared__ char smc[];
    uint32_t smb = smem_u32(smc);
    const uint32_t QHb = smb + A_QH, QLb = smb + A_QL;
    const uint32_t PHb = smb + A_PH, PLb = smb + A_PL;

    int tid = threadIdx.x;
    int w = tid >> 5, lane = tid & 31;
    int w16 = w * 16;
    int g = lane >> 2, tig = lane & 3;
    int tlane = lane >> 3, ri = lane & 7;

    int q0 = blockIdx.x * 64;
    int bh = blockIdx.y;
    int b = bh >> 4;

    const float* Mb = mask + (size_t)b * SS * SS;
    size_t bh_base = (size_t)bh * SS * 256;

    // ---- prologue: Q tile (group 0), stage(0) (group 1), stage(1) (group 2)
    {
        size_t qbase = bh_base + (size_t)q0 * 256;
        #pragma unroll
        for (int j = 0; j < 8; j++) {
            uint32_t o = j * 2048 + tid * 16;
            cp16(QHb + o, g_pqh + qbase + o);
            cp16(QLb + o, g_pql + qbase + o);
        }
        CP_COMMIT();
    }
    #pragma unroll
    for (int pre = 0; pre < 2; pre++) {
        size_t tbase = bh_base + (size_t)(pre * 32) * 256;
        uint32_t sb = smb + A_STG + pre * A_BUF;
        #pragma unroll
        for (int j = 0; j < 4; j++) {
            uint32_t o = j * 2048 + tid * 16;
            cp16(sb + 0     + o, g_pkh + tbase + o);
            cp16(sb + 8192  + o, g_pkl + tbase + o);
            cp16(sb + 16384 + o, g_pvh + tbase + o);
            cp16(sb + 24576 + o, g_pvl + tbase + o);
        }
        CP_COMMIT();
    }

    float o[16][4];
    #pragma unroll
    for (int j = 0; j < 16; j++) { o[j][0] = o[j][1] = o[j][2] = o[j][3] = 0.f; }
    float m_0 = -INFINITY, m_1 = -INFINITY, l_0 = 0.f, l_1 = 0.f;
    const float scale = 0.08838834764831845f;

    int arow = w16 + (tlane & 1) * 8 + ri;
    int acol_half = (tlane >> 1) * 16;
    int brow_in = (tlane >> 1) * 8 + ri;
    int bcol_half = (tlane & 1) * 16;
    int vrow_in = (tlane & 1) * 8 + ri;
    int vcol_half = (tlane >> 1) * 16;

    for (int it = 0; it < 64; it++) {
        int k0 = it * 32;
        uint32_t sb = smb + A_STG + (it & 1) * A_BUF;
        const uint32_t KHb = sb, KLb = sb + 8192, VHb = sb + 16384, VLb = sb + 24576;

        CP_WAIT1();
        __syncthreads();

        // ---- S = Q K^T (3-term split), warp covers 16 rows x 32 cols ----
        float s[4][4];
        #pragma unroll
        for (int j = 0; j < 4; j++) { s[j][0] = s[j][1] = s[j][2] = s[j][3] = 0.f; }

        #pragma unroll
        for (int ks = 0; ks < 8; ks++) {
            uint32_t aH[4], aL[4];
            uint32_t qoff = swz256(arow, ks * 32 + acol_half);
            ldsm4(aH, QHb + qoff);
            ldsm4(aL, QLb + qoff);
            uint32_t bHf[8], bLf[8];
            #pragma unroll
            for (int p = 0; p < 2; p++) {
                uint32_t koff = swz256(p * 16 + brow_in, ks * 32 + bcol_half);
                ldsm4(bHf + p * 4, KHb + koff);
                ldsm4(bLf + p * 4, KLb + koff);
            }
            #pragma unroll
            for (int j = 0; j < 4; j++) {
                uint32_t b0h = bHf[(j >> 1) * 4 + (j & 1) * 2], b1h = bHf[(j >> 1) * 4 + (j & 1) * 2 + 1];
                uint32_t b0l = bLf[(j >> 1) * 4 + (j & 1) * 2], b1l = bLf[(j >> 1) * 4 + (j & 1) * 2 + 1];
                mma16816(s[j], aH, b0h, b1h);
                mma16816(s[j], aL, b0h, b1h);
                mma16816(s[j], aH, b0l, b1l);
            }
        }

        // ---- online softmax (warp-local; rows w16+g and w16+g+8) ----
        const float* mr0 = Mb + (size_t)(q0 + w16 + g) * SS + k0;
        const float* mr1 = mr0 + (size_t)8 * SS;
        float mx0 = -INFINITY, mx1 = -INFINITY;
        #pragma unroll
        for (int j = 0; j < 4; j++) {
            float2 mk0 = *(const float2*)(mr0 + j * 8 + tig * 2);
            float2 mk1 = *(const float2*)(mr1 + j * 8 + tig * 2);
            s[j][0] = fmaf(s[j][0], scale, mk0.x);
            s[j][1] = fmaf(s[j][1], scale, mk0.y);
            s[j][2] = fmaf(s[j][2], scale, mk1.x);
            s[j][3] = fmaf(s[j][3], scale, mk1.y);
            mx0 = fmaxf(mx0, fmaxf(s[j][0], s[j][1]));
            mx1 = fmaxf(mx1, fmaxf(s[j][2], s[j][3]));
        }
        mx0 = fmaxf(mx0, __shfl_xor_sync(0xffffffffu, mx0, 1));
        mx0 = fmaxf(mx0, __shfl_xor_sync(0xffffffffu, mx0, 2));
        mx1 = fmaxf(mx1, __shfl_xor_sync(0xffffffffu, mx1, 1));
        mx1 = fmaxf(mx1, __shfl_xor_sync(0xffffffffu, mx1, 2));
        float mn0 = fmaxf(m_0, mx0), mn1 = fmaxf(m_1, mx1);
        float f0 = __expf(m_0 - mn0), f1 = __expf(m_1 - mn1);

        float sum0 = 0.f, sum1 = 0.f;
        #pragma unroll
        for (int j = 0; j < 4; j++) {
            float p00 = __expf(s[j][0] - mn0);
            float p01 = __expf(s[j][1] - mn0);
            float p10 = __expf(s[j][2] - mn1);
            float p11 = __expf(s[j][3] - mn1);
            sum0 += p00 + p01; sum1 += p10 + p11;
            float h00, l00, h01, l01, h10, l10, h11, l11;
            split1(p00, h00, l00); split1(p01, h01, l01);
            split1(p10, h10, l10); split1(p11, h11, l11);
            uint32_t off0 = (uint32_t)((w16 + g) * 80 + j * 16 + tig * 4);
            uint32_t off1 = (uint32_t)((w16 + g + 8) * 80 + j * 16 + tig * 4);
            *(uint32_t*)(smc + A_PH + off0) = pack_bf16(h00, h01);
            *(uint32_t*)(smc + A_PL + off0) = pack_bf16(l00, l01);
            *(uint32_t*)(smc + A_PH + off1) = pack_bf16(h10, h11);
            *(uint32_t*)(smc + A_PL + off1) = pack_bf16(l10, l11);
        }
        sum0 += __shfl_xor_sync(0xffffffffu, sum0, 1);
        sum0 += __shfl_xor_sync(0xffffffffu, sum0, 2);
        sum1 += __shfl_xor_sync(0xffffffffu, sum1, 1);
        sum1 += __shfl_xor_sync(0xffffffffu, sum1, 2);
        l_0 = l_0 * f0 + sum0; l_1 = l_1 * f1 + sum1;
        m_0 = mn0; m_1 = mn1;

        #pragma unroll
        for (int j = 0; j < 16; j++) {
            o[j][0] *= f0; o[j][1] *= f0;
            o[j][2] *= f1; o[j][3] *= f1;
        }
        __syncwarp();   // P visible to own warp's ldmatrix

        // ---- O += P V (3-term split), 16 rows x 128 cols, kdim 32 ----
        #pragma unroll
        for (int ks = 0; ks < 2; ks++) {
            uint32_t aH[4], aL[4];
            uint32_t poff = (uint32_t)(arow * 80 + ks * 32 + acol_half);
            ldsm4(aH, PHb + poff);
            ldsm4(aL, PLb + poff);
            #pragma unroll
            for (int p = 0; p < 8; p++) {
                uint32_t vH[4], vL[4];
                uint32_t voff = swz256(ks * 16 + vrow_in, p * 32 + vcol_half);
                ldsm4t(vH, VHb + voff);
                ldsm4t(vL, VLb + voff);
                int j0 = p * 2, j1 = p * 2 + 1;
                mma16816(o[j0], aH, vH[0], vH[1]);
                mma16816(o[j1], aH, vH[2], vH[3]);
                mma16816(o[j0], aL, vH[0], vH[1]);
                mma16816(o[j1], aL, vH[2], vH[3]);
                mma16816(o[j0], aH, vL[0], vL[1]);
                mma16816(o[j1], aH, vL[2], vL[3]);
            }
        }

        __syncthreads();   // all warps done reading stage buffer (it & 1)
        if (it + 2 < 64) {
            size_t tbase = bh_base + (size_t)((it + 2) * 32) * 256;
            uint32_t nb = smb + A_STG + (it & 1) * A_BUF;
            #pragma unroll
            for (int j = 0; j < 4; j++) {
                uint32_t oo = j * 2048 + tid * 16;
                cp16(nb + 0     + oo, g_pkh + tbase + oo);
                cp16(nb + 8192  + oo, g_pkl + tbase + oo);
                cp16(nb + 16384 + oo, g_pvh + tbase + oo);
                cp16(nb + 24576 + oo, g_pvl + tbase + oo);
            }
            CP_COMMIT();
        }
    }

    // ---- epilogue: O / l -> split-bf16 planes for the output projection ----
    int h = bh & 15;
    float inv0 = 1.0f / l_0, inv1 = 1.0f / l_1;
    size_t t0 = (size_t)(b * SS + q0 + w16 + g);
    size_t t1 = t0 + 8;
    #pragma unroll
    for (int j = 0; j < 16; j++) {
        int colg = h * HD + j * 8 + tig * 2;
        float v0 = o[j][0] * inv0, v1 = o[j][1] * inv0;
        float u0 = o[j][2] * inv1, u1 = o[j][3] * inv1;
        float h0, l0s, h1, l1s;
        split1(v0, h0, l0s); split1(v1, h1, l1s);
        *(uint32_t*)&g_ah[t0 * NF + colg] = pack_bf16(h0, h1);
        *(uint32_t*)&g_al[t0 * NF + colg] = pack_bf16(l0s, l1s);
        split1(u0, h0, l0s); split1(u1, h1, l1s);
        *(uint32_t*)&g_ah[t1 * NF + colg] = pack_bf16(h0, h1);
        *(uint32_t*)&g_al[t1 * NF + colg] = pack_bf16(l0s, l1s);
    }
}

// ---------------- launch ----------------------------------------------------
extern "C" void kernel_launch(void* const* d_in, const int* in_sizes, int n_in,
                              void* d_out, int out_size) {
    const float* x     = (const float*)d_in[0];
    const float* mask0 = (const float*)d_in[1];
    const float* wq    = (const float*)d_in[2];
    const float* wk    = (const float*)d_in[3];
    const float* wv    = (const float*)d_in[4];
    const float* wo    = (const float*)d_in[5];
    const float* qnw   = (const float*)d_in[6];
    const float* knw   = (const float*)d_in[7];
    float* out = (float*)d_out;

    __nv_bfloat16 *pxh, *pxl, *pw6h, *pw6l, *pwoh, *pwol, *pah, *pal;
    cudaGetSymbolAddress((void**)&pxh, g_xh);
    cudaGetSymbolAddress((void**)&pxl, g_xl);
    cudaGetSymbolAddress((void**)&pw6h, g_w6h);
    cudaGetSymbolAddress((void**)&pw6l, g_w6l);
    cudaGetSymbolAddress((void**)&pwoh, g_woh);
    cudaGetSymbolAddress((void**)&pwol, g_wol);
    cudaGetSymbolAddress((void**)&pah, g_ah);
    cudaGetSymbolAddress((void**)&pal, g_al);

    static bool attr_set = false;
    if (!attr_set) {
        cudaFuncSetAttribute(attn_mma_kernel, cudaFuncAttributeMaxDynamicSharedMemorySize,
                             SM_ATT_TOTAL);
        cudaFuncSetAttribute(gemm_bf16_kernel, cudaFuncAttributeMaxDynamicSharedMemorySize,
                             GSM_TOTAL);
        attr_set = true;
    }

    // 1. RoPE tables
    rope_table_kernel<<<(SS * 64 + 255) / 256, 256>>>();

    // 2. split-bf16 conversion of x and all weights
    conv_split_kernel<<<dim3((NT * DD + 255) / 256, 5), 256>>>(x, wq, wk, wv, wo);

    // 3. QKV projections (tensor-core split-bf16): [4096,192] x [6144,192]^T
    gemm_bf16_kernel<<<dim3(NT / 128, (3 * NF) / 64), 256, GSM_TOTAL>>>(
        pxh, pxl, pw6h, pw6l, DD, DD, DD, 0, out);

    // 4. per-head RMSNorm + RoPE + attention-plane emit
    norm_rope_kernel<<<dim3(HH, NT), 128>>>(qnw, knw);

    // 5. attention (mma.sync bf16 split, Br=64 Bc=32, 2 CTAs/SM)
    attn_mma_kernel<<<dim3(SS / 64, BB * HH), 128, SM_ATT_TOTAL>>>(mask0);

    // 6. output projection: [4096,2048] x [192,2048]^T -> d_out
    gemm_bf16_kernel<<<dim3(NT / 128, DD / 64), 256, GSM_TOTAL>>>(
        pah, pal, pwoh, pwol, NF, NF, NF, 1, out);
}

// round 7
// speedup vs baseline: 4.4496x; 1.0239x over previous
#include <cuda_runtime.h>
#include <cuda_bf16.h>
#include <math.h>
#include <stdint.h>

// Problem dims (fixed by reference)
#define BB 2
#define SS 2048
#define DD 192
#define HH 16
#define HD 128
#define NT (BB*SS)        // 4096 tokens
#define NF (HH*HD)        // 2048 features

// ---------------- scratch (device globals; no allocations allowed) ----------
__device__ float g_q[NT * NF];     // fp32 projection outputs (scratch)
__device__ float g_k[NT * NF];
__device__ float g_v[NT * NF];
__device__ float g_cos[SS * 64];
__device__ float g_sin[SS * 64];

// pre-swizzled split-bf16 planes for attention: [(b*HH+h)][s][256B row, 16B-chunk XOR (s&7)]
#define PLANE_BYTES ((size_t)NT * NF * 2)
__device__ __align__(1024) unsigned char g_pqh[PLANE_BYTES];
__device__ __align__(1024) unsigned char g_pql[PLANE_BYTES];
__device__ __align__(1024) unsigned char g_pkh[PLANE_BYTES];
__device__ __align__(1024) unsigned char g_pkl[PLANE_BYTES];
__device__ __align__(1024) unsigned char g_pvh[PLANE_BYTES];
__device__ __align__(1024) unsigned char g_pvl[PLANE_BYTES];

// linear split-bf16 planes for GEMMs
__device__ __align__(16) __nv_bfloat16 g_xh[NT * DD];       // x
__device__ __align__(16) __nv_bfloat16 g_xl[NT * DD];
__device__ __align__(16) __nv_bfloat16 g_w6h[3 * NF * DD];  // wq|wk|wv stacked
__device__ __align__(16) __nv_bfloat16 g_w6l[3 * NF * DD];
__device__ __align__(16) __nv_bfloat16 g_woh[DD * NF];      // wo
__device__ __align__(16) __nv_bfloat16 g_wol[DD * NF];
__device__ __align__(16) __nv_bfloat16 g_ah[(size_t)NT * NF]; // attention out
__device__ __align__(16) __nv_bfloat16 g_al[(size_t)NT * NF];

// plane byte offset for (bh, s, d)
__device__ __forceinline__ size_t plane_off(int bh, int s, int d) {
    int colb = d * 2;
    int sw = ((((colb >> 4) ^ (s & 7)) << 4) | (colb & 15));
    return ((size_t)bh * SS + s) * 256 + sw;
}

// =======================  warp-MMA helpers (generic PTX, sm_80+) ============
__device__ __forceinline__ uint32_t smem_u32(const void* p) {
    uint32_t a;
    asm("{ .reg .u64 t; cvta.to.shared.u64 t, %1; cvt.u32.u64 %0, t; }"
        : "=r"(a) : "l"(p));
    return a;
}

__device__ __forceinline__ void ldsm4(uint32_t* r, uint32_t addr) {
    asm volatile("ldmatrix.sync.aligned.m8n8.x4.shared.b16 {%0,%1,%2,%3}, [%4];"
        : "=r"(r[0]), "=r"(r[1]), "=r"(r[2]), "=r"(r[3]) : "r"(addr) : "memory");
}
__device__ __forceinline__ void ldsm4t(uint32_t* r, uint32_t addr) {
    asm volatile("ldmatrix.sync.aligned.m8n8.x4.trans.shared.b16 {%0,%1,%2,%3}, [%4];"
        : "=r"(r[0]), "=r"(r[1]), "=r"(r[2]), "=r"(r[3]) : "r"(addr) : "memory");
}

__device__ __forceinline__ void mma16816(float* c, const uint32_t* a, uint32_t b0, uint32_t b1) {
    asm volatile(
        "mma.sync.aligned.m16n8k16.row.col.f32.bf16.bf16.f32 "
        "{%0,%1,%2,%3}, {%4,%5,%6,%7}, {%8,%9}, {%0,%1,%2,%3};"
        : "+f"(c[0]), "+f"(c[1]), "+f"(c[2]), "+f"(c[3])
        : "r"(a[0]), "r"(a[1]), "r"(a[2]), "r"(a[3]), "r"(b0), "r"(b1));
}

__device__ __forceinline__ void cp16(uint32_t smem_dst, const void* gsrc) {
    asm volatile("cp.async.cg.shared.global [%0], [%1], 16;"
        :: "r"(smem_dst), "l"(gsrc) : "memory");
}
#define CP_COMMIT() asm volatile("cp.async.commit_group;" ::: "memory")
#define CP_WAIT1()  asm volatile("cp.async.wait_group 1;" ::: "memory")
#define CP_WAIT0()  asm volatile("cp.async.wait_group 0;" ::: "memory")

__device__ __forceinline__ uint32_t pack_bf16(float a, float b) {
    __nv_bfloat162 t = __floats2bfloat162_rn(a, b);
    return *(uint32_t*)&t;
}
__device__ __forceinline__ void split1(float x, float& hi, float& lo) {
    hi = __bfloat162float(__float2bfloat16(x));
    lo = x - hi;
}

// XOR swizzle at 16B granularity (row stride 256B)
__device__ __forceinline__ uint32_t swz256(int row, int colb) {
    return (uint32_t)(row * 256 + ((((colb >> 4) ^ (row & 7)) << 4) | (colb & 15)));
}

// ---------------- RoPE table (fp64-accurate) --------------------------------
__global__ void rope_table_kernel() {
    int i = blockIdx.x * blockDim.x + threadIdx.x;
    if (i >= SS * 64) return;
    int s = i >> 6, f = i & 63;
    double e = ((double)(2 * f) / 128.0) * 13.815510557964274;
    double invf = exp(-e);
    double ph = (double)s * invf;
    g_cos[i] = (float)cos(ph);
    g_sin[i] = (float)sin(ph);
}

// ---------------- split-conversion of x / wq / wk / wv / wo -----------------
__global__ __launch_bounds__(256) void conv_split_kernel(
    const float* __restrict__ x,  const float* __restrict__ wq,
    const float* __restrict__ wk, const float* __restrict__ wv,
    const float* __restrict__ wo)
{
    int z = blockIdx.y;
    int i = blockIdx.x * 256 + threadIdx.x;
    const float* src; __nv_bfloat16 *dh, *dl; int cnt;
    if (z == 0)      { src = x;  dh = g_xh;  dl = g_xl;  cnt = NT * DD; }
    else if (z == 1) { src = wq; dh = g_w6h; dl = g_w6l; cnt = NF * DD; }
    else if (z == 2) { src = wk; dh = g_w6h + NF * DD; dl = g_w6l + NF * DD; cnt = NF * DD; }
    else if (z == 3) { src = wv; dh = g_w6h + 2 * NF * DD; dl = g_w6l + 2 * NF * DD; cnt = NF * DD; }
    else             { src = wo; dh = g_woh; dl = g_wol; cnt = DD * NF; }
    if (i >= cnt) return;
    float v = src[i];
    float hi, lo;
    split1(v, hi, lo);
    dh[i] = __float2bfloat16(hi);
    dl[i] = __float2bfloat16(lo);
}

// ---------- split-bf16 tensor-core GEMM: C[M][N] = A[M][K] * B[N][K]^T ------
#define GSTG_AH 0
#define GSTG_AL 10240
#define GSTG_BH 20480
#define GSTG_BL 25600
#define GBUF    30720
#define GSM_TOTAL (2 * GBUF)

__global__ __launch_bounds__(256, 2) void gemm_bf16_kernel(
    const __nv_bfloat16* __restrict__ Ah, const __nv_bfloat16* __restrict__ Al,
    const __nv_bfloat16* __restrict__ Bh, const __nv_bfloat16* __restrict__ Bl,
    int lda, int ldb, int K, int mode, float* __restrict__ Cout)
{
    extern __shared__ char gsm[];
    uint32_t smb = smem_u32(gsm);
    int tid = threadIdx.x;
    int w = tid >> 5, lane = tid & 31;
    int wm = w >> 1, wn = w & 1;
    int g = lane >> 2, tig = lane & 3;
    int tlane = lane >> 3, ri = lane & 7;
    int m0 = blockIdx.x * 128, n0 = blockIdx.y * 64;
    int nk = K >> 5;

    float c[2][4][4] = {};

    int a_r = (tlane & 1) * 8 + ri;
    int a_cb = (tlane >> 1) * 16;
    int b_r = (tlane >> 1) * 8 + ri;
    int b_cb = (tlane & 1) * 16;

    auto load_buf = [&](int kt, uint32_t sb) {
        int k0e = kt << 5;
        for (int i = tid; i < 512; i += 256) {
            int r = i >> 2, cB = (i & 3) * 16;
            uint32_t d = sb + r * 80 + cB;
            const char* sh = (const char*)(Ah + (size_t)(m0 + r) * lda + k0e) + cB;
            const char* sl = (const char*)(Al + (size_t)(m0 + r) * lda + k0e) + cB;
            cp16(d + GSTG_AH, sh);
            cp16(d + GSTG_AL, sl);
        }
        for (int i = tid; i < 256; i += 256) {
            int r = i >> 2, cB = (i & 3) * 16;
            uint32_t d = sb + r * 80 + cB;
            const char* sh = (const char*)(Bh + (size_t)(n0 + r) * ldb + k0e) + cB;
            const char* sl = (const char*)(Bl + (size_t)(n0 + r) * ldb + k0e) + cB;
            cp16(d + GSTG_BH, sh);
            cp16(d + GSTG_BL, sl);
        }
    };

    load_buf(0, smb);
    CP_COMMIT();

    for (int kt = 0; kt < nk; kt++) {
        uint32_t sb = smb + (kt & 1) * GBUF;
        if (kt + 1 < nk) {
            __syncthreads();
            load_buf(kt + 1, smb + ((kt + 1) & 1) * GBUF);
            CP_COMMIT();
            CP_WAIT1();
        } else {
            CP_WAIT0();
        }
        __syncthreads();

        #pragma unroll
        for (int ks = 0; ks < 2; ks++) {
            uint32_t aH[2][4], aL[2][4];
            #pragma unroll
            for (int mf = 0; mf < 2; mf++) {
                uint32_t ad = sb + (uint32_t)((wm * 32 + mf * 16 + a_r) * 80 + ks * 32 + a_cb);
                ldsm4(aH[mf], ad + GSTG_AH);
                ldsm4(aL[mf], ad + GSTG_AL);
            }
            uint32_t bH[2][4], bL[2][4];
            #pragma unroll
            for (int nt = 0; nt < 2; nt++) {
                uint32_t bd = sb + (uint32_t)((wn * 32 + nt * 16 + b_r) * 80 + ks * 32 + b_cb);
                ldsm4(bH[nt], bd + GSTG_BH);
                ldsm4(bL[nt], bd + GSTG_BL);
            }
            #pragma unroll
            for (int mf = 0; mf < 2; mf++) {
                #pragma unroll
                for (int nt = 0; nt < 2; nt++) {
                    float* c0 = c[mf][nt * 2];
                    float* c1 = c[mf][nt * 2 + 1];
                    mma16816(c0, aH[mf], bH[nt][0], bH[nt][1]);
                    mma16816(c0, aL[mf], bH[nt][0], bH[nt][1]);
                    mma16816(c0, aH[mf], bL[nt][0], bL[nt][1]);
                    mma16816(c1, aH[mf], bH[nt][2], bH[nt][3]);
                    mma16816(c1, aL[mf], bH[nt][2], bH[nt][3]);
                    mma16816(c1, aH[mf], bL[nt][2], bL[nt][3]);
                }
            }
        }
    }

    #pragma unroll
    for (int mf = 0; mf < 2; mf++) {
        int row0 = m0 + wm * 32 + mf * 16 + g;
        #pragma unroll
        for (int nn = 0; nn < 4; nn++) {
            int colg = n0 + wn * 32 + nn * 8 + tig * 2;
            float2 v0 = make_float2(c[mf][nn][0], c[mf][nn][1]);
            float2 v1 = make_float2(c[mf][nn][2], c[mf][nn][3]);
            if (mode == 0) {
                int which = colg >> 11, cc = colg & 2047;
                float* dstp = (which == 0) ? g_q : (which == 1) ? g_k : g_v;
                *(float2*)(dstp + (size_t)row0 * NF + cc) = v0;
                *(float2*)(dstp + (size_t)(row0 + 8) * NF + cc) = v1;
            } else {
                *(float2*)(Cout + (size_t)row0 * DD + colg) = v0;
                *(float2*)(Cout + (size_t)(row0 + 8) * DD + colg) = v1;
            }
        }
    }
}

// ------ per-head RMSNorm + RoPE + split-bf16 plane emit, 4 heads/block ------
__global__ __launch_bounds__(512) void norm_rope_kernel(
    const float* __restrict__ qw, const float* __restrict__ kw)
{
    int grp = threadIdx.x >> 7;        // 0..3 head sub-index
    int d = threadIdx.x & 127;
    int h = blockIdx.x * 4 + grp;
    int t = blockIdx.y;
    int s = t & (SS - 1);
    int b = t >> 11;
    int bh = b * HH + h;

    const float* qp = g_q + (size_t)t * NF + h * HD;
    const float* kp = g_k + (size_t)t * NF + h * HD;
    const float* vp = g_v + (size_t)t * NF + h * HD;
    float q = qp[d];
    float k = kp[d];
    float v = vp[d];

    float sq = q * q, sk = k * k;
    #pragma unroll
    for (int m = 16; m; m >>= 1) {
        sq += __shfl_xor_sync(0xffffffffu, sq, m);
        sk += __shfl_xor_sync(0xffffffffu, sk, m);
    }
    __shared__ float rq[4][4], rk[4][4];
    __shared__ float shq[4][HD], shk[4][HD];
    int wid = d >> 5, lane = d & 31;
    if (lane == 0) { rq[grp][wid] = sq; rk[grp][wid] = sk; }
    __syncthreads();
    float ssq = rq[grp][0] + rq[grp][1] + rq[grp][2] + rq[grp][3];
    float ssk = rk[grp][0] + rk[grp][1] + rk[grp][2] + rk[grp][3];
    float rinvq = rsqrtf(ssq * (1.0f / HD) + 1e-6f);
    float rinvk = rsqrtf(ssk * (1.0f / HD) + 1e-6f);
    float qn = q * rinvq * qw[d];
    float kn = k * rinvk * kw[d];
    shq[grp][d] = qn; shk[grp][d] = kn;
    __syncthreads();

    int f = d & 63;
    float c = g_cos[s * 64 + f];
    float sn = g_sin[s * 64 + f];
    float qo, ko;
    if (d < 64) {
        qo = qn * c - shq[grp][d + 64] * sn;
        ko = kn * c - shk[grp][d + 64] * sn;
    } else {
        qo = qn * c + shq[grp][d - 64] * sn;
        ko = kn * c + shk[grp][d - 64] * sn;
    }

    size_t po = plane_off(bh, s, d);
    float hi, lo;
    split1(qo, hi, lo);
    *(__nv_bfloat16*)(g_pqh + po) = __float2bfloat16(hi);
    *(__nv_bfloat16*)(g_pql + po) = __float2bfloat16(lo);
    split1(ko, hi, lo);
    *(__nv_bfloat16*)(g_pkh + po) = __float2bfloat16(hi);
    *(__nv_bfloat16*)(g_pkl + po) = __float2bfloat16(lo);
    split1(v, hi, lo);
    *(__nv_bfloat16*)(g_pvh + po) = __float2bfloat16(hi);
    *(__nv_bfloat16*)(g_pvl + po) = __float2bfloat16(lo);
}

// ===== mma.sync flash attention, Br=64 x Bc=32, Q in regs, 2 CTAs/SM ========
// smem: P planes + two 32KB K/V stage buffers (Q staged through buffer 0)
#define A_PH 0                       // 64 rows x 80B = 5120B
#define A_PL 5120
#define A_STG 10240
#define A_BUF 32768
#define SM_ATT_TOTAL (A_STG + 2 * A_BUF)    // 75776

__global__ __launch_bounds__(128, 2) void attn_mma_kernel(const float* __restrict__ mask)
{
    extern __shared__ char smc[];
    uint32_t smb = smem_u32(smc);
    const uint32_t PHb = smb + A_PH, PLb = smb + A_PL;

    int tid = threadIdx.x;
    int w = tid >> 5, lane = tid & 31;
    int w16 = w * 16;
    int g = lane >> 2, tig = lane & 3;
    int tlane = lane >> 3, ri = lane & 7;

    int q0 = blockIdx.x * 64;
    int bh = blockIdx.y;
    int b = bh >> 4;

    const float* Mb = mask + (size_t)b * SS * SS;
    size_t bh_base = (size_t)bh * SS * 256;

    int arow = w16 + (tlane & 1) * 8 + ri;
    int acol_half = (tlane >> 1) * 16;
    int brow_in = (tlane >> 1) * 8 + ri;
    int bcol_half = (tlane & 1) * 16;
    int vrow_in = (tlane & 1) * 8 + ri;
    int vcol_half = (tlane >> 1) * 16;

    // ---- prologue A: Q tile -> stage buffer 0 -> registers ----
    uint32_t qH[8][4], qL[8][4];
    {
        uint32_t sb0 = smb + A_STG;
        size_t qbase = bh_base + (size_t)q0 * 256;
        #pragma unroll
        for (int j = 0; j < 8; j++) {
            uint32_t o = j * 2048 + tid * 16;
            cp16(sb0 + o, g_pqh + qbase + o);
            cp16(sb0 + 16384 + o, g_pql + qbase + o);
        }
        CP_COMMIT();
        CP_WAIT0();
        __syncthreads();
        #pragma unroll
        for (int ks = 0; ks < 8; ks++) {
            uint32_t qoff = swz256(arow, ks * 32 + acol_half);
            ldsm4(qH[ks], sb0 + qoff);
            ldsm4(qL[ks], sb0 + 16384 + qoff);
        }
        __syncthreads();   // Q reads done before K/V overwrite buffer 0
    }

    // ---- prologue B: stage K/V for it=0,1 ----
    #pragma unroll
    for (int pre = 0; pre < 2; pre++) {
        size_t tbase = bh_base + (size_t)(pre * 32) * 256;
        uint32_t sb = smb + A_STG + pre * A_BUF;
        #pragma unroll
        for (int j = 0; j < 4; j++) {
            uint32_t o = j * 2048 + tid * 16;
            cp16(sb + 0     + o, g_pkh + tbase + o);
            cp16(sb + 8192  + o, g_pkl + tbase + o);
            cp16(sb + 16384 + o, g_pvh + tbase + o);
            cp16(sb + 24576 + o, g_pvl + tbase + o);
        }
        CP_COMMIT();
    }

    float o[16][4];
    #pragma unroll
    for (int j = 0; j < 16; j++) { o[j][0] = o[j][1] = o[j][2] = o[j][3] = 0.f; }
    float m_0 = -INFINITY, m_1 = -INFINITY, l_0 = 0.f, l_1 = 0.f;
    const float scale = 0.08838834764831845f;

    for (int it = 0; it < 64; it++) {
        int k0 = it * 32;
        uint32_t sb = smb + A_STG + (it & 1) * A_BUF;
        const uint32_t KHb = sb, KLb = sb + 8192, VHb = sb + 16384, VLb = sb + 24576;

        // prefetch mask rows for this tile (independent of MMA results)
        const float* mr0 = Mb + (size_t)(q0 + w16 + g) * SS + k0;
        const float* mr1 = mr0 + (size_t)8 * SS;
        float2 mk0r[4], mk1r[4];
        #pragma unroll
        for (int j = 0; j < 4; j++) {
            mk0r[j] = *(const float2*)(mr0 + j * 8 + tig * 2);
            mk1r[j] = *(const float2*)(mr1 + j * 8 + tig * 2);
        }

        CP_WAIT1();
        __syncthreads();

        // ---- S = Q K^T (3-term split), warp covers 16 rows x 32 cols ----
        float s[4][4];
        #pragma unroll
        for (int j = 0; j < 4; j++) { s[j][0] = s[j][1] = s[j][2] = s[j][3] = 0.f; }

        #pragma unroll
        for (int ks = 0; ks < 8; ks++) {
            uint32_t bHf[8], bLf[8];
            #pragma unroll
            for (int p = 0; p < 2; p++) {
                uint32_t koff = swz256(p * 16 + brow_in, ks * 32 + bcol_half);
                ldsm4(bHf + p * 4, KHb + koff);
                ldsm4(bLf + p * 4, KLb + koff);
            }
            #pragma unroll
            for (int j = 0; j < 4; j++) {
                uint32_t b0h = bHf[(j >> 1) * 4 + (j & 1) * 2], b1h = bHf[(j >> 1) * 4 + (j & 1) * 2 + 1];
                uint32_t b0l = bLf[(j >> 1) * 4 + (j & 1) * 2], b1l = bLf[(j >> 1) * 4 + (j & 1) * 2 + 1];
                mma16816(s[j], qH[ks], b0h, b1h);
                mma16816(s[j], qL[ks], b0h, b1h);
                mma16816(s[j], qH[ks], b0l, b1l);
            }
        }

        // ---- online softmax (warp-local; rows w16+g and w16+g+8) ----
        float mx0 = -INFINITY, mx1 = -INFINITY;
        #pragma unroll
        for (int j = 0; j < 4; j++) {
            s[j][0] = fmaf(s[j][0], scale, mk0r[j].x);
            s[j][1] = fmaf(s[j][1], scale, mk0r[j].y);
            s[j][2] = fmaf(s[j][2], scale, mk1r[j].x);
            s[j][3] = fmaf(s[j][3], scale, mk1r[j].y);
            mx0 = fmaxf(mx0, fmaxf(s[j][0], s[j][1]));
            mx1 = fmaxf(mx1, fmaxf(s[j][2], s[j][3]));
        }
        mx0 = fmaxf(mx0, __shfl_xor_sync(0xffffffffu, mx0, 1));
        mx0 = fmaxf(mx0, __shfl_xor_sync(0xffffffffu, mx0, 2));
        mx1 = fmaxf(mx1, __shfl_xor_sync(0xffffffffu, mx1, 1));
        mx1 = fmaxf(mx1, __shfl_xor_sync(0xffffffffu, mx1, 2));
        float mn0 = fmaxf(m_0, mx0), mn1 = fmaxf(m_1, mx1);
        float f0 = __expf(m_0 - mn0), f1 = __expf(m_1 - mn1);

        float sum0 = 0.f, sum1 = 0.f;
        #pragma unroll
        for (int j = 0; j < 4; j++) {
            float p00 = __expf(s[j][0] - mn0);
            float p01 = __expf(s[j][1] - mn0);
            float p10 = __expf(s[j][2] - mn1);
            float p11 = __expf(s[j][3] - mn1);
            sum0 += p00 + p01; sum1 += p10 + p11;
            float h00, l00, h01, l01, h10, l10, h11, l11;
            split1(p00, h00, l00); split1(p01, h01, l01);
            split1(p10, h10, l10); split1(p11, h11, l11);
            uint32_t off0 = (uint32_t)((w16 + g) * 80 + j * 16 + tig * 4);
            uint32_t off1 = (uint32_t)((w16 + g + 8) * 80 + j * 16 + tig * 4);
            *(uint32_t*)(smc + A_PH + off0) = pack_bf16(h00, h01);
            *(uint32_t*)(smc + A_PL + off0) = pack_bf16(l00, l01);
            *(uint32_t*)(smc + A_PH + off1) = pack_bf16(h10, h11);
            *(uint32_t*)(smc + A_PL + off1) = pack_bf16(l10, l11);
        }
        sum0 += __shfl_xor_sync(0xffffffffu, sum0, 1);
        sum0 += __shfl_xor_sync(0xffffffffu, sum0, 2);
        sum1 += __shfl_xor_sync(0xffffffffu, sum1, 1);
        sum1 += __shfl_xor_sync(0xffffffffu, sum1, 2);
        l_0 = l_0 * f0 + sum0; l_1 = l_1 * f1 + sum1;
        m_0 = mn0; m_1 = mn1;

        #pragma unroll
        for (int j = 0; j < 16; j++) {
            o[j][0] *= f0; o[j][1] *= f0;
            o[j][2] *= f1; o[j][3] *= f1;
        }
        __syncwarp();   // P visible to own warp's ldmatrix

        // ---- O += P V (3-term split), 16 rows x 128 cols, kdim 32 ----
        #pragma unroll
        for (int ks = 0; ks < 2; ks++) {
            uint32_t aH[4], aL[4];
            uint32_t poff = (uint32_t)(arow * 80 + ks * 32 + acol_half);
            ldsm4(aH, PHb + poff);
            ldsm4(aL, PLb + poff);
            #pragma unroll
            for (int p = 0; p < 8; p++) {
                uint32_t vH[4], vL[4];
                uint32_t voff = swz256(ks * 16 + vrow_in, p * 32 + vcol_half);
                ldsm4t(vH, VHb + voff);
                ldsm4t(vL, VLb + voff);
                int j0 = p * 2, j1 = p * 2 + 1;
                mma16816(o[j0], aH, vH[0], vH[1]);
                mma16816(o[j1], aH, vH[2], vH[3]);
                mma16816(o[j0], aL, vH[0], vH[1]);
                mma16816(o[j1], aL, vH[2], vH[3]);
                mma16816(o[j0], aH, vL[0], vL[1]);
                mma16816(o[j1], aH, vL[2], vL[3]);
            }
        }

        __syncthreads();   // all warps done reading stage buffer (it & 1)
        if (it + 2 < 64) {
            size_t tbase = bh_base + (size_t)((it + 2) * 32) * 256;
            uint32_t nb = smb + A_STG + (it & 1) * A_BUF;
            #pragma unroll
            for (int j = 0; j < 4; j++) {
                uint32_t oo = j * 2048 + tid * 16;
                cp16(nb + 0     + oo, g_pkh + tbase + oo);
                cp16(nb + 8192  + oo, g_pkl + tbase + oo);
                cp16(nb + 16384 + oo, g_pvh + tbase + oo);
                cp16(nb + 24576 + oo, g_pvl + tbase + oo);
            }
            CP_COMMIT();
        }
    }

    // ---- epilogue: O / l -> split-bf16 planes for the output projection ----
    int h = bh & 15;
    float inv0 = 1.0f / l_0, inv1 = 1.0f / l_1;
    size_t t0 = (size_t)(b * SS + q0 + w16 + g);
    size_t t1 = t0 + 8;
    #pragma unroll
    for (int j = 0; j < 16; j++) {
        int colg = h * HD + j * 8 + tig * 2;
        float v0 = o[j][0] * inv0, v1 = o[j][1] * inv0;
        float u0 = o[j][2] * inv1, u1 = o[j][3] * inv1;
        float h0, l0s, h1, l1s;
        split1(v0, h0, l0s); split1(v1, h1, l1s);
        *(uint32_t*)&g_ah[t0 * NF + colg] = pack_bf16(h0, h1);
        *(uint32_t*)&g_al[t0 * NF + colg] = pack_bf16(l0s, l1s);
        split1(u0, h0, l0s); split1(u1, h1, l1s);
        *(uint32_t*)&g_ah[t1 * NF + colg] = pack_bf16(h0, h1);
        *(uint32_t*)&g_al[t1 * NF + colg] = pack_bf16(l0s, l1s);
    }
}

// ---------------- launch ----------------------------------------------------
extern "C" void kernel_launch(void* const* d_in, const int* in_sizes, int n_in,
                              void* d_out, int out_size) {
    const float* x     = (const float*)d_in[0];
    const float* mask0 = (const float*)d_in[1];
    const float* wq    = (const float*)d_in[2];
    const float* wk    = (const float*)d_in[3];
    const float* wv    = (const float*)d_in[4];
    const float* wo    = (const float*)d_in[5];
    const float* qnw   = (const float*)d_in[6];
    const float* knw   = (const float*)d_in[7];
    float* out = (float*)d_out;

    __nv_bfloat16 *pxh, *pxl, *pw6h, *pw6l, *pwoh, *pwol, *pah, *pal;
    cudaGetSymbolAddress((void**)&pxh, g_xh);
    cudaGetSymbolAddress((void**)&pxl, g_xl);
    cudaGetSymbolAddress((void**)&pw6h, g_w6h);
    cudaGetSymbolAddress((void**)&pw6l, g_w6l);
    cudaGetSymbolAddress((void**)&pwoh, g_woh);
    cudaGetSymbolAddress((void**)&pwol, g_wol);
    cudaGetSymbolAddress((void**)&pah, g_ah);
    cudaGetSymbolAddress((void**)&pal, g_al);

    static bool attr_set = false;
    if (!attr_set) {
        cudaFuncSetAttribute(attn_mma_kernel, cudaFuncAttributeMaxDynamicSharedMemorySize,
                             SM_ATT_TOTAL);
        cudaFuncSetAttribute(gemm_bf16_kernel, cudaFuncAttributeMaxDynamicSharedMemorySize,
                             GSM_TOTAL);
        attr_set = true;
    }

    // 1. RoPE tables
    rope_table_kernel<<<(SS * 64 + 255) / 256, 256>>>();

    // 2. split-bf16 conversion of x and all weights
    conv_split_kernel<<<dim3((NT * DD + 255) / 256, 5), 256>>>(x, wq, wk, wv, wo);

    // 3. QKV projections (tensor-core split-bf16): [4096,192] x [6144,192]^T
    gemm_bf16_kernel<<<dim3(NT / 128, (3 * NF) / 64), 256, GSM_TOTAL>>>(
        pxh, pxl, pw6h, pw6l, DD, DD, DD, 0, out);

    // 4. per-head RMSNorm + RoPE + attention-plane emit (4 heads/block)
    norm_rope_kernel<<<dim3(HH / 4, NT), 512>>>(qnw, knw);

    // 5. attention (mma.sync bf16 split, Q-in-regs, 2 CTAs/SM)
    attn_mma_kernel<<<dim3(SS / 64, BB * HH), 128, SM_ATT_TOTAL>>>(mask0);

    // 6. output projection: [4096,2048] x [192,2048]^T -> d_out
    gemm_bf16_kernel<<<dim3(NT / 128, DD / 64), 256, GSM_TOTAL>>>(
        pah, pal, pwoh, pwol, NF, NF, NF, 1, out);
}